// round 11
// baseline (speedup 1.0000x reference)
#include <cuda_runtime.h>
#include <math.h>

// Fixed shapes: B=2048, P=4, H=16, K=48, D=4, G=64
#define PH 16
#define PK 48
#define PD 4
#define LOG2PI 1.83787706640934548356f

#define SA 66              // shared row stride (floats): conflict-free
#define WPB 4              // warps (problems) per block

__device__ __forceinline__ float warp_sum(float v) {
#pragma unroll
    for (int o = 16; o > 0; o >>= 1) v += __shfl_xor_sync(0xffffffffu, v, o);
    return v;
}

// Interleaved butterfly reductions: force N independent SHFL chains in flight.
__device__ __forceinline__ void warp_sum2(float& a, float& b) {
#pragma unroll
    for (int o = 16; o > 0; o >>= 1) {
        float ta = __shfl_xor_sync(0xffffffffu, a, o);
        float tb = __shfl_xor_sync(0xffffffffu, b, o);
        a += ta; b += tb;
    }
}
__device__ __forceinline__ void warp_sum3(float& a, float& b, float& c) {
#pragma unroll
    for (int o = 16; o > 0; o >>= 1) {
        float ta = __shfl_xor_sync(0xffffffffu, a, o);
        float tb = __shfl_xor_sync(0xffffffffu, b, o);
        float tc = __shfl_xor_sync(0xffffffffu, c, o);
        a += ta; b += tb; c += tc;
    }
}
__device__ __forceinline__ void warp_sum4(float& a, float& b, float& c, float& d) {
#pragma unroll
    for (int o = 16; o > 0; o >>= 1) {
        float ta = __shfl_xor_sync(0xffffffffu, a, o);
        float tb = __shfl_xor_sync(0xffffffffu, b, o);
        float tc = __shfl_xor_sync(0xffffffffu, c, o);
        float td = __shfl_xor_sync(0xffffffffu, d, o);
        a += ta; b += tb; c += tc; d += td;
    }
}

// 64-length dot of two shared rows (8-byte aligned)
__device__ __forceinline__ float dot64(const float* p, const float* q) {
    const float2* P = reinterpret_cast<const float2*>(p);
    const float2* Q = reinterpret_cast<const float2*>(q);
    float s0 = 0.0f, s1 = 0.0f;
#pragma unroll
    for (int g = 0; g < 32; g++) {
        float2 u = P[g], v = Q[g];
        s0 = fmaf(u.x, v.x, s0);
        s1 = fmaf(u.y, v.y, s1);
    }
    return s0 + s1;
}

__global__ __launch_bounds__(128, 5) void integ_kernel(
    const float* __restrict__ input_i,      // [BP, D]
    const float* __restrict__ Prev_coefs,   // [H, BP, H]
    const float* __restrict__ Prev_biases,  // [H, BP]
    const float* __restrict__ LP,           // [BP]
    const float* __restrict__ Log_factors,  // [BP]
    const float* __restrict__ obs_var,      // [K, BP, D]
    const float* __restrict__ hid_var,      // [K, BP, H]
    const float* __restrict__ next_var,     // [K, BP, H]
    const float* __restrict__ rec_biases,   // [K, BP]
    float* __restrict__ out, int BP)
{
    __shared__ float sAt[WPB][16 * SA];   // A^T   (16 rows x 64 gaussians)
    __shared__ float sBt[WPB][17 * SA];   // [Bm|c]^T (17 rows x 64)
    __shared__ float sMm[WPB][16 * 17];   // Gram M -> Cholesky L (col 16 = 1/diag)
    __shared__ float sXx[WPB][17 * 17];   // N -> X = M^{-1} A^T [Bm|c], column-major

    const int warp = threadIdx.x >> 5;
    const int lane = threadIdx.x & 31;
    const int prob = blockIdx.x * WPB + warp;
    if (prob >= BP) return;

    float* At = sAt[warp];
    float* Bt = sBt[warp];
    float* sM = sMm[warp];
    float* sX = sXx[warp];

    const float4 xi = *reinterpret_cast<const float4*>(input_i + (size_t)prob * PD);

    // ---- load rows into shared (lane owns gaussians g0=lane, g1=lane+32) ----
    {
        float b0[16], b1[16], c0, c1;
        if (lane < PH) {
            const float4* p = reinterpret_cast<const float4*>(
                Prev_coefs + ((size_t)lane * BP + prob) * PH);
#pragma unroll
            for (int q = 0; q < 4; q++) {
                float4 v = p[q];
                At[(4*q+0)*SA + lane] = v.x; At[(4*q+1)*SA + lane] = v.y;
                At[(4*q+2)*SA + lane] = v.z; At[(4*q+3)*SA + lane] = v.w;
            }
#pragma unroll
            for (int i = 0; i < 16; i++) b0[i] = 0.0f;
            c0 = Prev_biases[(size_t)lane * BP + prob];
        } else {
            int k = lane - PH;
            const float4* p  = reinterpret_cast<const float4*>(
                hid_var + ((size_t)k * BP + prob) * PH);
            const float4* q4 = reinterpret_cast<const float4*>(
                next_var + ((size_t)k * BP + prob) * PH);
#pragma unroll
            for (int q = 0; q < 4; q++) {
                float4 v = p[q];
                At[(4*q+0)*SA + lane] = v.x; At[(4*q+1)*SA + lane] = v.y;
                At[(4*q+2)*SA + lane] = v.z; At[(4*q+3)*SA + lane] = v.w;
                float4 w = q4[q];
                b0[4*q+0] = w.x; b0[4*q+1] = w.y; b0[4*q+2] = w.z; b0[4*q+3] = w.w;
            }
            const float4 ov = *reinterpret_cast<const float4*>(
                obs_var + ((size_t)k * BP + prob) * PD);
            c0 = rec_biases[(size_t)k * BP + prob]
               + ov.x*xi.x + ov.y*xi.y + ov.z*xi.z + ov.w*xi.w;
        }
        {
            int k = lane + (32 - PH);
            const float4* p  = reinterpret_cast<const float4*>(
                hid_var + ((size_t)k * BP + prob) * PH);
            const float4* q4 = reinterpret_cast<const float4*>(
                next_var + ((size_t)k * BP + prob) * PH);
#pragma unroll
            for (int q = 0; q < 4; q++) {
                float4 v = p[q];
                At[(4*q+0)*SA + lane + 32] = v.x; At[(4*q+1)*SA + lane + 32] = v.y;
                At[(4*q+2)*SA + lane + 32] = v.z; At[(4*q+3)*SA + lane + 32] = v.w;
                float4 w = q4[q];
                b1[4*q+0] = w.x; b1[4*q+1] = w.y; b1[4*q+2] = w.z; b1[4*q+3] = w.w;
            }
            const float4 ov = *reinterpret_cast<const float4*>(
                obs_var + ((size_t)k * BP + prob) * PD);
            c1 = rec_biases[(size_t)k * BP + prob]
               + ov.x*xi.x + ov.y*xi.y + ov.z*xi.z + ov.w*xi.w;
        }
#pragma unroll
        for (int i = 0; i < 16; i++) {
            Bt[i*SA + lane]      = b0[i];
            Bt[i*SA + lane + 32] = b1[i];
        }
        Bt[16*SA + lane]      = c0;
        Bt[16*SA + lane + 32] = c1;
    }
    __syncwarp();

    // ---- M = A^T A : 2x2 register tiles; 36 tiles over 8x8 pair grid ----
#pragma unroll
    for (int rep = 0; rep < 2; rep++) {
        int t = lane + 32 * rep;
        if (t < 36) {
            int ti = 0, tt = t;
            while (tt >= 8 - ti) { tt -= 8 - ti; ++ti; }
            int tj = ti + tt;
            int i0 = 2*ti, i1 = i0 + 1, j0 = 2*tj, j1 = j0 + 1;
            const float2* Pi0 = reinterpret_cast<const float2*>(At + i0*SA);
            const float2* Pi1 = reinterpret_cast<const float2*>(At + i1*SA);
            const float2* Pj0 = reinterpret_cast<const float2*>(At + j0*SA);
            const float2* Pj1 = reinterpret_cast<const float2*>(At + j1*SA);
            float s00 = 0.0f, s01 = 0.0f, s10 = 0.0f, s11 = 0.0f;
#pragma unroll
            for (int g = 0; g < 32; g++) {
                float2 u0 = Pi0[g], u1 = Pi1[g], w0 = Pj0[g], w1 = Pj1[g];
                s00 = fmaf(u0.x, w0.x, s00); s00 = fmaf(u0.y, w0.y, s00);
                s01 = fmaf(u0.x, w1.x, s01); s01 = fmaf(u0.y, w1.y, s01);
                s10 = fmaf(u1.x, w0.x, s10); s10 = fmaf(u1.y, w0.y, s10);
                s11 = fmaf(u1.x, w1.x, s11); s11 = fmaf(u1.y, w1.y, s11);
            }
            sM[i0*17 + j0] = s00; sM[j0*17 + i0] = s00;
            sM[i0*17 + j1] = s01; sM[j1*17 + i0] = s01;
            sM[i1*17 + j0] = s10; sM[j0*17 + i1] = s10;
            sM[i1*17 + j1] = s11; sM[j1*17 + i1] = s11;
        }
    }
    __syncwarp();

    // ==== ONE barrier-free region: N-Gram + bn2 (throughput) overlapped with
    //      the register Cholesky (latency chain). They are independent. ====

    // ---- N = A^T Bm : 2x2 tiles over (8 i-pairs) x (8 k-pairs), zero rows skipped ----
#pragma unroll
    for (int rep = 0; rep < 2; rep++) {
        int t = lane + 32 * rep;           // 0..63, uniform tile code
        int ti = t & 7, tk = t >> 3;
        int i0 = 2*ti, i1 = i0 + 1, k0 = 2*tk, k1 = k0 + 1;
        // Bm columns are zero on gaussians 0..15 -> sum over g in [16,64)
        const float2* Pi0 = reinterpret_cast<const float2*>(At + i0*SA + 16);
        const float2* Pi1 = reinterpret_cast<const float2*>(At + i1*SA + 16);
        const float2* Qk0 = reinterpret_cast<const float2*>(Bt + k0*SA + 16);
        const float2* Qk1 = reinterpret_cast<const float2*>(Bt + k1*SA + 16);
        float s00 = 0.0f, s01 = 0.0f, s10 = 0.0f, s11 = 0.0f;
#pragma unroll
        for (int g = 0; g < 24; g++) {
            float2 u0 = Pi0[g], u1 = Pi1[g], w0 = Qk0[g], w1 = Qk1[g];
            s00 = fmaf(u0.x, w0.x, s00); s00 = fmaf(u0.y, w0.y, s00);
            s01 = fmaf(u0.x, w1.x, s01); s01 = fmaf(u0.y, w1.y, s01);
            s10 = fmaf(u1.x, w0.x, s10); s10 = fmaf(u1.y, w0.y, s10);
            s11 = fmaf(u1.x, w1.x, s11); s11 = fmaf(u1.y, w1.y, s11);
        }
        sX[k0*17 + i0] = s00; sX[k1*17 + i0] = s01;
        sX[k0*17 + i1] = s10; sX[k1*17 + i1] = s11;
    }
    // bias column k = 16 (full 64 gaussians): lanes 0..7, i-pair per lane
    if (lane < 8) {
        int i0 = 2*lane, i1 = i0 + 1;
        const float2* Pi0 = reinterpret_cast<const float2*>(At + i0*SA);
        const float2* Pi1 = reinterpret_cast<const float2*>(At + i1*SA);
        const float2* Qc  = reinterpret_cast<const float2*>(Bt + 16*SA);
        float s0 = 0.0f, s1 = 0.0f;
#pragma unroll
        for (int g = 0; g < 32; g++) {
            float2 u0 = Pi0[g], u1 = Pi1[g], w = Qc[g];
            s0 = fmaf(u0.x, w.x, s0); s0 = fmaf(u0.y, w.y, s0);
            s1 = fmaf(u1.x, w.x, s1); s1 = fmaf(u1.y, w.y, s1);
        }
        sX[16*17 + i0] = s0;
        sX[16*17 + i1] = s1;
    }

    // ---- column norms of [Bm|c] : lane k<17 owns column k ----
    float bn2 = 0.0f;
    if (lane < 17) bn2 = dot64(Bt + lane*SA, Bt + lane*SA);

    // ---- right-looking register Cholesky: lane i owns row i of M ----
    float neglog = 0.0f;
    {
        float m[16];
        int li = lane & 15;
#pragma unroll
        for (int k = 0; k < 16; k++) m[k] = sM[li*17 + k];

#pragma unroll
        for (int j = 0; j < 16; j++) {
            float d   = __shfl_sync(0xffffffffu, m[j], j);
            float Ljj = sqrtf(d);
            float rL  = __fdividef(1.0f, Ljj);
            float lij = m[j] * rL;           // L_ij on lane i (valid for i > j)
            if (lane == j) {
                neglog = -__logf(Ljj);
                sM[j*17 + 16] = rL;          // reciprocal diag for the solve
            } else if (lane > j && lane < 16) {
                sM[lane*17 + j] = lij;       // spill column j of L
            }
#pragma unroll
            for (int k = j + 1; k < 16; k++) {
                float lkj = __shfl_sync(0xffffffffu, lij, k);
                m[k] = fmaf(-lij, lkj, m[k]);
            }
        }
    }
    __syncwarp();

    // ---- solve M X = N per column (lane k<17); s_own = ||P col_k||^2 via qn ----
    float s_own = 0.0f;
    if (lane < 17) {
        float y[16];
#pragma unroll
        for (int i = 0; i < 16; i++) y[i] = sX[lane*17 + i];
        // forward: y := L^{-1} N_k  (parity-split partial sums)
#pragma unroll
        for (int i = 0; i < 16; i++) {
            float p0 = 0.0f, p1 = 0.0f;
#pragma unroll
            for (int t = 0; t < i; t++) {
                if (t & 1) p1 = fmaf(sM[i*17 + t], y[t], p1);
                else       p0 = fmaf(sM[i*17 + t], y[t], p0);
            }
            y[i] = (y[i] - (p0 + p1)) * sM[i*17 + 16];
        }
        float qn = 0.0f;
#pragma unroll
        for (int i = 0; i < 16; i++) qn = fmaf(y[i], y[i], qn);
        s_own = bn2 - qn;       // ||(I - Q1 Q1^T) col_k||^2
        // backward: y := L^{-T} y
#pragma unroll
        for (int i = 15; i >= 0; i--) {
            float p0 = 0.0f, p1 = 0.0f;
#pragma unroll
            for (int t = 15; t > i; t--) {
                if (t & 1) p1 = fmaf(sM[t*17 + i], y[t], p1);
                else       p0 = fmaf(sM[t*17 + i], y[t], p0);
            }
            y[i] = (y[i] - (p0 + p1)) * sM[i*17 + 16];
        }
#pragma unroll
        for (int i = 0; i < 16; i++) sX[lane*17 + i] = y[i];
    }
    __syncwarp();

    // ---- projection: PB = Bm - A X, Pc = c - A x_c (back into registers) ----
    float b0[16], b1[16], c0, c1;
#pragma unroll
    for (int i = 0; i < 16; i++) {
        b0[i] = Bt[i*SA + lane];
        b1[i] = Bt[i*SA + lane + 32];
    }
    c0 = Bt[16*SA + lane];
    c1 = Bt[16*SA + lane + 32];
#pragma unroll
    for (int i = 0; i < 16; i++) {
        float ai0 = At[i*SA + lane];
        float ai1 = At[i*SA + lane + 32];
#pragma unroll
        for (int k = 0; k < 16; k++) {
            float xv = sX[k*17 + i];
            b0[k] = fmaf(-ai0, xv, b0[k]);
            b1[k] = fmaf(-ai1, xv, b1[k]);
        }
        float xc = sX[16*17 + i];
        c0 = fmaf(-ai0, xc, c0);
        c1 = fmaf(-ai1, xc, c1);
    }

    float pc2 = __shfl_sync(0xffffffffu, s_own, 16);   // ||Pc||^2

    // ---- Householder QR on PB (slarfg convention), norms downdated ----
    // Trailing-column reductions in QUADS (warp_sum4): four independent SHFL
    // chains in flight; static tail fuses leftover columns with the bias column.
#pragma unroll
    for (int j = 0; j < 16; j++) {
        float sj    = __shfl_sync(0xffffffffu, s_own, j);   // ||col j rows>=j||^2
        float alpha = __shfl_sync(0xffffffffu, b0[j], j);
        sj = fmaxf(sj, 1e-30f);
        float beta = -copysignf(sqrtf(sj), alpha);
        float tau  = __fdividef(beta - alpha, beta);
        float inv  = __fdividef(1.0f, alpha - beta);

        float v0 = (lane == j) ? 1.0f : ((lane > j) ? b0[j] * inv : 0.0f);
        float v1 = b1[j] * inv;

        if (lane == j)      b0[j] = beta;
        else if (lane > j)  b0[j] = 0.0f;
        b1[j] = 0.0f;

        float xc = fmaf(v0, c0, v1 * c1);       // bias-column partial

        int k = j + 1;
#pragma unroll
        for (; k + 3 < 16; k += 4) {
            float xa = fmaf(v0, b0[k],   v1 * b1[k]);
            float xb = fmaf(v0, b0[k+1], v1 * b1[k+1]);
            float xd = fmaf(v0, b0[k+2], v1 * b1[k+2]);
            float xe = fmaf(v0, b0[k+3], v1 * b1[k+3]);
            warp_sum4(xa, xb, xd, xe);
            float wa = tau * xa, wb = tau * xb, wd = tau * xd, we = tau * xe;
            b0[k]   = fmaf(-wa, v0, b0[k]);   b1[k]   = fmaf(-wa, v1, b1[k]);
            b0[k+1] = fmaf(-wb, v0, b0[k+1]); b1[k+1] = fmaf(-wb, v1, b1[k+1]);
            b0[k+2] = fmaf(-wd, v0, b0[k+2]); b1[k+2] = fmaf(-wd, v1, b1[k+2]);
            b0[k+3] = fmaf(-we, v0, b0[k+3]); b1[k+3] = fmaf(-we, v1, b1[k+3]);
            float ra = __shfl_sync(0xffffffffu, b0[k],   j);
            float rb = __shfl_sync(0xffffffffu, b0[k+1], j);
            float rd = __shfl_sync(0xffffffffu, b0[k+2], j);
            float re = __shfl_sync(0xffffffffu, b0[k+3], j);
            if (lane == k)   s_own = fmaf(-ra, ra, s_own);
            if (lane == k+1) s_own = fmaf(-rb, rb, s_own);
            if (lane == k+2) s_own = fmaf(-rd, rd, s_own);
            if (lane == k+3) s_own = fmaf(-re, re, s_own);
        }
        // static tail: (16-k) in {0,1,2,3} b-columns fused with the bias column
        int rem = 16 - k;
        if (rem == 3) {
            float xa = fmaf(v0, b0[k],   v1 * b1[k]);
            float xb = fmaf(v0, b0[k+1], v1 * b1[k+1]);
            float xd = fmaf(v0, b0[k+2], v1 * b1[k+2]);
            warp_sum4(xa, xb, xd, xc);
            float wa = tau * xa, wb = tau * xb, wd = tau * xd, wc = tau * xc;
            b0[k]   = fmaf(-wa, v0, b0[k]);   b1[k]   = fmaf(-wa, v1, b1[k]);
            b0[k+1] = fmaf(-wb, v0, b0[k+1]); b1[k+1] = fmaf(-wb, v1, b1[k+1]);
            b0[k+2] = fmaf(-wd, v0, b0[k+2]); b1[k+2] = fmaf(-wd, v1, b1[k+2]);
            c0 = fmaf(-wc, v0, c0);           c1 = fmaf(-wc, v1, c1);
            float ra = __shfl_sync(0xffffffffu, b0[k],   j);
            float rb = __shfl_sync(0xffffffffu, b0[k+1], j);
            float rd = __shfl_sync(0xffffffffu, b0[k+2], j);
            if (lane == k)   s_own = fmaf(-ra, ra, s_own);
            if (lane == k+1) s_own = fmaf(-rb, rb, s_own);
            if (lane == k+2) s_own = fmaf(-rd, rd, s_own);
        } else if (rem == 2) {
            float xa = fmaf(v0, b0[k],   v1 * b1[k]);
            float xb = fmaf(v0, b0[k+1], v1 * b1[k+1]);
            warp_sum3(xa, xb, xc);
            float wa = tau * xa, wb = tau * xb, wc = tau * xc;
            b0[k]   = fmaf(-wa, v0, b0[k]);   b1[k]   = fmaf(-wa, v1, b1[k]);
            b0[k+1] = fmaf(-wb, v0, b0[k+1]); b1[k+1] = fmaf(-wb, v1, b1[k+1]);
            c0 = fmaf(-wc, v0, c0);           c1 = fmaf(-wc, v1, c1);
            float ra = __shfl_sync(0xffffffffu, b0[k],   j);
            float rb = __shfl_sync(0xffffffffu, b0[k+1], j);
            if (lane == k)   s_own = fmaf(-ra, ra, s_own);
            if (lane == k+1) s_own = fmaf(-rb, rb, s_own);
        } else if (rem == 1) {
            float xa = fmaf(v0, b0[k], v1 * b1[k]);
            warp_sum2(xa, xc);
            float wa = tau * xa, wc = tau * xc;
            b0[k] = fmaf(-wa, v0, b0[k]);  b1[k] = fmaf(-wa, v1, b1[k]);
            c0 = fmaf(-wc, v0, c0);        c1 = fmaf(-wc, v1, c1);
            float ra = __shfl_sync(0xffffffffu, b0[k], j);
            if (lane == k) s_own = fmaf(-ra, ra, s_own);
        } else {
            float wc = tau * warp_sum(xc);
            c0 = fmaf(-wc, v0, c0);
            c1 = fmaf(-wc, v1, c1);
        }
    }

    // final reductions fused: lc1 and nb2 in one pass
    float lc1 = neglog;
    float nb2 = (lane < 16) ? c0 * c0 : 0.0f;
    warp_sum2(lc1, nb2);
    float resid = fmaxf(pc2 - nb2, 0.0f);
    float LC = lc1 - 0.5f * ((float)(PK - PH) * LOG2PI + resid);

    // ---- outputs: Next_coefs [H,BP,H] | Next_biases [H,BP] | LP_new [BP] ----
    const size_t off1 = (size_t)PH * BP * PH;
    const size_t off2 = off1 + (size_t)PH * BP;

    if (lane < 16) {
        float4* po = reinterpret_cast<float4*>(out + ((size_t)lane * BP + prob) * PH);
        po[0] = make_float4(b0[0],  b0[1],  b0[2],  b0[3]);
        po[1] = make_float4(b0[4],  b0[5],  b0[6],  b0[7]);
        po[2] = make_float4(b0[8],  b0[9],  b0[10], b0[11]);
        po[3] = make_float4(b0[12], b0[13], b0[14], b0[15]);
        out[off1 + (size_t)lane * BP + prob] = c0;
    }
    if (lane == 0) {
        out[off2 + prob] = LP[prob] + LC + Log_factors[prob];
    }
}

extern "C" void kernel_launch(void* const* d_in, const int* in_sizes, int n_in,
                              void* d_out, int out_size) {
    const float* input_i     = (const float*)d_in[0];
    const float* Prev_coefs  = (const float*)d_in[1];
    const float* Prev_biases = (const float*)d_in[2];
    const float* LP          = (const float*)d_in[3];
    const float* Log_factors = (const float*)d_in[4];
    const float* obs_var     = (const float*)d_in[5];
    const float* hid_var     = (const float*)d_in[6];
    const float* next_var    = (const float*)d_in[7];
    const float* rec_biases  = (const float*)d_in[8];

    int BP = in_sizes[3];                     // B * P (size of LP)
    int blocks = (BP + WPB - 1) / WPB;        // 1 problem per warp, 4 warps/block
    integ_kernel<<<blocks, WPB * 32>>>(input_i, Prev_coefs, Prev_biases, LP, Log_factors,
                                       obs_var, hid_var, next_var, rec_biases,
                                       (float*)d_out, BP);
}

// round 12
// speedup vs baseline: 1.0067x; 1.0067x over previous
#include <cuda_runtime.h>
#include <math.h>

// Fixed shapes: B=2048, P=4, H=16, K=48, D=4, G=64
#define PH 16
#define PK 48
#define PD 4
#define LOG2PI 1.83787706640934548356f

#define SA 66              // shared row stride (floats): conflict-free
#define WPB 4              // warps (problems) per block

__device__ __forceinline__ float warp_sum(float v) {
#pragma unroll
    for (int o = 16; o > 0; o >>= 1) v += __shfl_xor_sync(0xffffffffu, v, o);
    return v;
}

// Two interleaved butterfly reductions: forces 2 independent SHFL chains in flight.
__device__ __forceinline__ void warp_sum2(float& a, float& b) {
#pragma unroll
    for (int o = 16; o > 0; o >>= 1) {
        float ta = __shfl_xor_sync(0xffffffffu, a, o);
        float tb = __shfl_xor_sync(0xffffffffu, b, o);
        a += ta; b += tb;
    }
}

// 64-length dot of two shared rows (8-byte aligned)
__device__ __forceinline__ float dot64(const float* p, const float* q) {
    const float2* P = reinterpret_cast<const float2*>(p);
    const float2* Q = reinterpret_cast<const float2*>(q);
    float s0 = 0.0f, s1 = 0.0f;
#pragma unroll
    for (int g = 0; g < 32; g++) {
        float2 u = P[g], v = Q[g];
        s0 = fmaf(u.x, v.x, s0);
        s1 = fmaf(u.y, v.y, s1);
    }
    return s0 + s1;
}

__global__ __launch_bounds__(128, 5) void integ_kernel(
    const float* __restrict__ input_i,      // [BP, D]
    const float* __restrict__ Prev_coefs,   // [H, BP, H]
    const float* __restrict__ Prev_biases,  // [H, BP]
    const float* __restrict__ LP,           // [BP]
    const float* __restrict__ Log_factors,  // [BP]
    const float* __restrict__ obs_var,      // [K, BP, D]
    const float* __restrict__ hid_var,      // [K, BP, H]
    const float* __restrict__ next_var,     // [K, BP, H]
    const float* __restrict__ rec_biases,   // [K, BP]
    float* __restrict__ out, int BP)
{
    __shared__ float sAt[WPB][16 * SA];   // A^T   (16 rows x 64 gaussians)
    __shared__ float sBt[WPB][17 * SA];   // [Bm|c]^T (17 rows x 64)
    __shared__ float sMm[WPB][16 * 17];   // Gram M -> Cholesky L (col 16 = 1/diag)
    __shared__ float sXx[WPB][17 * 17];   // N -> X = M^{-1} A^T [Bm|c], column-major

    const int warp = threadIdx.x >> 5;
    const int lane = threadIdx.x & 31;
    const int prob = blockIdx.x * WPB + warp;
    if (prob >= BP) return;

    float* At = sAt[warp];
    float* Bt = sBt[warp];
    float* sM = sMm[warp];
    float* sX = sXx[warp];

    const float4 xi = *reinterpret_cast<const float4*>(input_i + (size_t)prob * PD);

    // ---- load rows into shared (lane owns gaussians g0=lane, g1=lane+32) ----
    {
        float b0[16], b1[16], c0, c1;
        if (lane < PH) {
            const float4* p = reinterpret_cast<const float4*>(
                Prev_coefs + ((size_t)lane * BP + prob) * PH);
#pragma unroll
            for (int q = 0; q < 4; q++) {
                float4 v = p[q];
                At[(4*q+0)*SA + lane] = v.x; At[(4*q+1)*SA + lane] = v.y;
                At[(4*q+2)*SA + lane] = v.z; At[(4*q+3)*SA + lane] = v.w;
            }
#pragma unroll
            for (int i = 0; i < 16; i++) b0[i] = 0.0f;
            c0 = Prev_biases[(size_t)lane * BP + prob];
        } else {
            int k = lane - PH;
            const float4* p  = reinterpret_cast<const float4*>(
                hid_var + ((size_t)k * BP + prob) * PH);
            const float4* q4 = reinterpret_cast<const float4*>(
                next_var + ((size_t)k * BP + prob) * PH);
#pragma unroll
            for (int q = 0; q < 4; q++) {
                float4 v = p[q];
                At[(4*q+0)*SA + lane] = v.x; At[(4*q+1)*SA + lane] = v.y;
                At[(4*q+2)*SA + lane] = v.z; At[(4*q+3)*SA + lane] = v.w;
                float4 w = q4[q];
                b0[4*q+0] = w.x; b0[4*q+1] = w.y; b0[4*q+2] = w.z; b0[4*q+3] = w.w;
            }
            const float4 ov = *reinterpret_cast<const float4*>(
                obs_var + ((size_t)k * BP + prob) * PD);
            c0 = rec_biases[(size_t)k * BP + prob]
               + ov.x*xi.x + ov.y*xi.y + ov.z*xi.z + ov.w*xi.w;
        }
        {
            int k = lane + (32 - PH);
            const float4* p  = reinterpret_cast<const float4*>(
                hid_var + ((size_t)k * BP + prob) * PH);
            const float4* q4 = reinterpret_cast<const float4*>(
                next_var + ((size_t)k * BP + prob) * PH);
#pragma unroll
            for (int q = 0; q < 4; q++) {
                float4 v = p[q];
                At[(4*q+0)*SA + lane + 32] = v.x; At[(4*q+1)*SA + lane + 32] = v.y;
                At[(4*q+2)*SA + lane + 32] = v.z; At[(4*q+3)*SA + lane + 32] = v.w;
                float4 w = q4[q];
                b1[4*q+0] = w.x; b1[4*q+1] = w.y; b1[4*q+2] = w.z; b1[4*q+3] = w.w;
            }
            const float4 ov = *reinterpret_cast<const float4*>(
                obs_var + ((size_t)k * BP + prob) * PD);
            c1 = rec_biases[(size_t)k * BP + prob]
               + ov.x*xi.x + ov.y*xi.y + ov.z*xi.z + ov.w*xi.w;
        }
#pragma unroll
        for (int i = 0; i < 16; i++) {
            Bt[i*SA + lane]      = b0[i];
            Bt[i*SA + lane + 32] = b1[i];
        }
        Bt[16*SA + lane]      = c0;
        Bt[16*SA + lane + 32] = c1;
    }
    __syncwarp();

    // ---- M = A^T A : 2x2 register tiles; 36 tiles over 8x8 pair grid ----
#pragma unroll
    for (int rep = 0; rep < 2; rep++) {
        int t = lane + 32 * rep;
        if (t < 36) {
            int ti = 0, tt = t;
            while (tt >= 8 - ti) { tt -= 8 - ti; ++ti; }
            int tj = ti + tt;
            int i0 = 2*ti, i1 = i0 + 1, j0 = 2*tj, j1 = j0 + 1;
            const float2* Pi0 = reinterpret_cast<const float2*>(At + i0*SA);
            const float2* Pi1 = reinterpret_cast<const float2*>(At + i1*SA);
            const float2* Pj0 = reinterpret_cast<const float2*>(At + j0*SA);
            const float2* Pj1 = reinterpret_cast<const float2*>(At + j1*SA);
            float s00 = 0.0f, s01 = 0.0f, s10 = 0.0f, s11 = 0.0f;
#pragma unroll
            for (int g = 0; g < 32; g++) {
                float2 u0 = Pi0[g], u1 = Pi1[g], w0 = Pj0[g], w1 = Pj1[g];
                s00 = fmaf(u0.x, w0.x, s00); s00 = fmaf(u0.y, w0.y, s00);
                s01 = fmaf(u0.x, w1.x, s01); s01 = fmaf(u0.y, w1.y, s01);
                s10 = fmaf(u1.x, w0.x, s10); s10 = fmaf(u1.y, w0.y, s10);
                s11 = fmaf(u1.x, w1.x, s11); s11 = fmaf(u1.y, w1.y, s11);
            }
            sM[i0*17 + j0] = s00; sM[j0*17 + i0] = s00;
            sM[i0*17 + j1] = s01; sM[j1*17 + i0] = s01;
            sM[i1*17 + j0] = s10; sM[j0*17 + i1] = s10;
            sM[i1*17 + j1] = s11; sM[j1*17 + i1] = s11;
        }
    }
    __syncwarp();

    // ==== ONE barrier-free region: N-Gram + bn2 (throughput) overlapped with
    //      the register Cholesky (latency chain). They are independent. ====

    // ---- N = A^T Bm : 2x2 tiles over (8 i-pairs) x (8 k-pairs), zero rows skipped ----
#pragma unroll
    for (int rep = 0; rep < 2; rep++) {
        int t = lane + 32 * rep;           // 0..63, uniform tile code
        int ti = t & 7, tk = t >> 3;
        int i0 = 2*ti, i1 = i0 + 1, k0 = 2*tk, k1 = k0 + 1;
        // Bm columns are zero on gaussians 0..15 -> sum over g in [16,64)
        const float2* Pi0 = reinterpret_cast<const float2*>(At + i0*SA + 16);
        const float2* Pi1 = reinterpret_cast<const float2*>(At + i1*SA + 16);
        const float2* Qk0 = reinterpret_cast<const float2*>(Bt + k0*SA + 16);
        const float2* Qk1 = reinterpret_cast<const float2*>(Bt + k1*SA + 16);
        float s00 = 0.0f, s01 = 0.0f, s10 = 0.0f, s11 = 0.0f;
#pragma unroll
        for (int g = 0; g < 24; g++) {
            float2 u0 = Pi0[g], u1 = Pi1[g], w0 = Qk0[g], w1 = Qk1[g];
            s00 = fmaf(u0.x, w0.x, s00); s00 = fmaf(u0.y, w0.y, s00);
            s01 = fmaf(u0.x, w1.x, s01); s01 = fmaf(u0.y, w1.y, s01);
            s10 = fmaf(u1.x, w0.x, s10); s10 = fmaf(u1.y, w0.y, s10);
            s11 = fmaf(u1.x, w1.x, s11); s11 = fmaf(u1.y, w1.y, s11);
        }
        sX[k0*17 + i0] = s00; sX[k1*17 + i0] = s01;
        sX[k0*17 + i1] = s10; sX[k1*17 + i1] = s11;
    }
    // bias column k = 16 (full 64 gaussians): lanes 0..7, i-pair per lane
    if (lane < 8) {
        int i0 = 2*lane, i1 = i0 + 1;
        const float2* Pi0 = reinterpret_cast<const float2*>(At + i0*SA);
        const float2* Pi1 = reinterpret_cast<const float2*>(At + i1*SA);
        const float2* Qc  = reinterpret_cast<const float2*>(Bt + 16*SA);
        float s0 = 0.0f, s1 = 0.0f;
#pragma unroll
        for (int g = 0; g < 32; g++) {
            float2 u0 = Pi0[g], u1 = Pi1[g], w = Qc[g];
            s0 = fmaf(u0.x, w.x, s0); s0 = fmaf(u0.y, w.y, s0);
            s1 = fmaf(u1.x, w.x, s1); s1 = fmaf(u1.y, w.y, s1);
        }
        sX[16*17 + i0] = s0;
        sX[16*17 + i1] = s1;
    }

    // ---- column norms of [Bm|c] : lane k<17 owns column k ----
    float bn2 = 0.0f;
    if (lane < 17) bn2 = dot64(Bt + lane*SA, Bt + lane*SA);

    // ---- right-looking register Cholesky: lane i owns row i of M ----
    // rsqrt-based: no sqrt/div on the chain; lc1 term = -0.5*log(d_j).
    float neglog = 0.0f;
    {
        float m[16];
        int li = lane & 15;
#pragma unroll
        for (int k = 0; k < 16; k++) m[k] = sM[li*17 + k];

#pragma unroll
        for (int j = 0; j < 16; j++) {
            float d   = __shfl_sync(0xffffffffu, m[j], j);
            float rL  = rsqrtf(d);
            float lij = m[j] * rL;           // L_ij on lane i (valid for i > j)
            if (lane == j) {
                neglog = -0.5f * __logf(d);  // == -log(sqrt(d))
                sM[j*17 + 16] = rL;          // reciprocal diag for the solve
            } else if (lane > j && lane < 16) {
                sM[lane*17 + j] = lij;       // spill column j of L
            }
#pragma unroll
            for (int k = j + 1; k < 16; k++) {
                float lkj = __shfl_sync(0xffffffffu, lij, k);
                m[k] = fmaf(-lij, lkj, m[k]);
            }
        }
    }
    __syncwarp();

    // ---- solve M X = N per column (lane k<17); s_own = ||P col_k||^2 via qn ----
    float s_own = 0.0f;
    if (lane < 17) {
        float y[16];
#pragma unroll
        for (int i = 0; i < 16; i++) y[i] = sX[lane*17 + i];
        // forward: y := L^{-1} N_k  (parity-split partial sums)
#pragma unroll
        for (int i = 0; i < 16; i++) {
            float p0 = 0.0f, p1 = 0.0f;
#pragma unroll
            for (int t = 0; t < i; t++) {
                if (t & 1) p1 = fmaf(sM[i*17 + t], y[t], p1);
                else       p0 = fmaf(sM[i*17 + t], y[t], p0);
            }
            y[i] = (y[i] - (p0 + p1)) * sM[i*17 + 16];
        }
        float qn = 0.0f;
#pragma unroll
        for (int i = 0; i < 16; i++) qn = fmaf(y[i], y[i], qn);
        s_own = bn2 - qn;       // ||(I - Q1 Q1^T) col_k||^2
        // backward: y := L^{-T} y
#pragma unroll
        for (int i = 15; i >= 0; i--) {
            float p0 = 0.0f, p1 = 0.0f;
#pragma unroll
            for (int t = 15; t > i; t--) {
                if (t & 1) p1 = fmaf(sM[t*17 + i], y[t], p1);
                else       p0 = fmaf(sM[t*17 + i], y[t], p0);
            }
            y[i] = (y[i] - (p0 + p1)) * sM[i*17 + 16];
        }
#pragma unroll
        for (int i = 0; i < 16; i++) sX[lane*17 + i] = y[i];
    }
    __syncwarp();

    // ---- projection: PB = Bm - A X, Pc = c - A x_c (back into registers) ----
    float b0[16], b1[16], c0, c1;
#pragma unroll
    for (int i = 0; i < 16; i++) {
        b0[i] = Bt[i*SA + lane];
        b1[i] = Bt[i*SA + lane + 32];
    }
    c0 = Bt[16*SA + lane];
    c1 = Bt[16*SA + lane + 32];
#pragma unroll
    for (int i = 0; i < 16; i++) {
        float ai0 = At[i*SA + lane];
        float ai1 = At[i*SA + lane + 32];
#pragma unroll
        for (int k = 0; k < 16; k++) {
            float xv = sX[k*17 + i];
            b0[k] = fmaf(-ai0, xv, b0[k]);
            b1[k] = fmaf(-ai1, xv, b1[k]);
        }
        float xc = sX[16*17 + i];
        c0 = fmaf(-ai0, xc, c0);
        c1 = fmaf(-ai1, xc, c1);
    }

    float pc2 = __shfl_sync(0xffffffffu, s_own, 16);   // ||Pc||^2

    // ---- Householder QR on PB (slarfg convention), norms downdated ----
    // Pairs of trailing columns (warp_sum2). R_{j,k} recovered as bjk - w via a
    // prefetched shfl issued in parallel with the butterfly (bit-identical to
    // post-update shfl since v_j = 1), keeping the s_own downdate off the chain.
#pragma unroll
    for (int j = 0; j < 16; j++) {
        float sj    = __shfl_sync(0xffffffffu, s_own, j);   // ||col j rows>=j||^2
        float alpha = __shfl_sync(0xffffffffu, b0[j], j);
        sj = fmaxf(sj, 1e-30f);
        float beta = -copysignf(sqrtf(sj), alpha);
        float tau  = __fdividef(beta - alpha, beta);
        float inv  = __fdividef(1.0f, alpha - beta);

        float v0 = (lane == j) ? 1.0f : ((lane > j) ? b0[j] * inv : 0.0f);
        float v1 = b1[j] * inv;

        if (lane == j)      b0[j] = beta;
        else if (lane > j)  b0[j] = 0.0f;
        b1[j] = 0.0f;

        float xc = fmaf(v0, c0, v1 * c1);       // bias-column partial (off-chain)

        int k = j + 1;
#pragma unroll
        for (; k + 1 < 16; k += 2) {
            float bja = __shfl_sync(0xffffffffu, b0[k],   j);  // pre-update row-j vals
            float bjb = __shfl_sync(0xffffffffu, b0[k+1], j);
            float xa = fmaf(v0, b0[k],   v1 * b1[k]);
            float xb = fmaf(v0, b0[k+1], v1 * b1[k+1]);
            warp_sum2(xa, xb);
            float wa = tau * xa, wb = tau * xb;
            b0[k]   = fmaf(-wa, v0, b0[k]);   b1[k]   = fmaf(-wa, v1, b1[k]);
            b0[k+1] = fmaf(-wb, v0, b0[k+1]); b1[k+1] = fmaf(-wb, v1, b1[k+1]);
            float ra = bja - wa;              // == R_{j,k}   (v_j = 1)
            float rb = bjb - wb;              // == R_{j,k+1}
            if (lane == k)   s_own = fmaf(-ra, ra, s_own);
            if (lane == k+1) s_own = fmaf(-rb, rb, s_own);
        }
        if (k < 16) {
            // last odd trailing column paired with the bias column
            float bja = __shfl_sync(0xffffffffu, b0[k], j);
            float xa = fmaf(v0, b0[k], v1 * b1[k]);
            warp_sum2(xa, xc);
            float wa = tau * xa, wc = tau * xc;
            b0[k] = fmaf(-wa, v0, b0[k]);  b1[k] = fmaf(-wa, v1, b1[k]);
            c0 = fmaf(-wc, v0, c0);        c1 = fmaf(-wc, v1, c1);
            float ra = bja - wa;
            if (lane == k) s_own = fmaf(-ra, ra, s_own);
        } else {
            float wc = tau * warp_sum(xc);
            c0 = fmaf(-wc, v0, c0);
            c1 = fmaf(-wc, v1, c1);
        }
    }

    // final reductions fused: lc1 and nb2 in one pass
    float lc1 = neglog;
    float nb2 = (lane < 16) ? c0 * c0 : 0.0f;
    warp_sum2(lc1, nb2);
    float resid = fmaxf(pc2 - nb2, 0.0f);
    float LC = lc1 - 0.5f * ((float)(PK - PH) * LOG2PI + resid);

    // ---- outputs: Next_coefs [H,BP,H] | Next_biases [H,BP] | LP_new [BP] ----
    const size_t off1 = (size_t)PH * BP * PH;
    const size_t off2 = off1 + (size_t)PH * BP;

    if (lane < 16) {
        float4* po = reinterpret_cast<float4*>(out + ((size_t)lane * BP + prob) * PH);
        po[0] = make_float4(b0[0],  b0[1],  b0[2],  b0[3]);
        po[1] = make_float4(b0[4],  b0[5],  b0[6],  b0[7]);
        po[2] = make_float4(b0[8],  b0[9],  b0[10], b0[11]);
        po[3] = make_float4(b0[12], b0[13], b0[14], b0[15]);
        out[off1 + (size_t)lane * BP + prob] = c0;
    }
    if (lane == 0) {
        out[off2 + prob] = LP[prob] + LC + Log_factors[prob];
    }
}

extern "C" void kernel_launch(void* const* d_in, const int* in_sizes, int n_in,
                              void* d_out, int out_size) {
    const float* input_i     = (const float*)d_in[0];
    const float* Prev_coefs  = (const float*)d_in[1];
    const float* Prev_biases = (const float*)d_in[2];
    const float* LP          = (const float*)d_in[3];
    const float* Log_factors = (const float*)d_in[4];
    const float* obs_var     = (const float*)d_in[5];
    const float* hid_var     = (const float*)d_in[6];
    const float* next_var    = (const float*)d_in[7];
    const float* rec_biases  = (const float*)d_in[8];

    int BP = in_sizes[3];                     // B * P (size of LP)
    int blocks = (BP + WPB - 1) / WPB;        // 1 problem per warp, 4 warps/block
    integ_kernel<<<blocks, WPB * 32>>>(input_i, Prev_coefs, Prev_biases, LP, Log_factors,
                                       obs_var, hid_var, next_var, rec_biases,
                                       (float*)d_out, BP);
}

// round 13
// speedup vs baseline: 1.0072x; 1.0005x over previous
#include <cuda_runtime.h>
#include <math.h>

// Fixed shapes: B=2048, P=4, H=16, K=48, D=4, G=64
#define PH 16
#define PK 48
#define PD 4
#define LOG2PI 1.83787706640934548356f

#define SA 66              // shared row stride (floats): conflict-free

__device__ __forceinline__ float warp_sum(float v) {
#pragma unroll
    for (int o = 16; o > 0; o >>= 1) v += __shfl_xor_sync(0xffffffffu, v, o);
    return v;
}

// Two interleaved butterfly reductions: forces 2 independent SHFL chains in flight.
__device__ __forceinline__ void warp_sum2(float& a, float& b) {
#pragma unroll
    for (int o = 16; o > 0; o >>= 1) {
        float ta = __shfl_xor_sync(0xffffffffu, a, o);
        float tb = __shfl_xor_sync(0xffffffffu, b, o);
        a += ta; b += tb;
    }
}

// 64-length dot of two shared rows (8-byte aligned)
__device__ __forceinline__ float dot64(const float* p, const float* q) {
    const float2* P = reinterpret_cast<const float2*>(p);
    const float2* Q = reinterpret_cast<const float2*>(q);
    float s0 = 0.0f, s1 = 0.0f;
#pragma unroll
    for (int g = 0; g < 32; g++) {
        float2 u = P[g], v = Q[g];
        s0 = fmaf(u.x, v.x, s0);
        s1 = fmaf(u.y, v.y, s1);
    }
    return s0 + s1;
}

__global__ __launch_bounds__(32, 20) void integ_kernel(
    const float* __restrict__ input_i,      // [BP, D]
    const float* __restrict__ Prev_coefs,   // [H, BP, H]
    const float* __restrict__ Prev_biases,  // [H, BP]
    const float* __restrict__ LP,           // [BP]
    const float* __restrict__ Log_factors,  // [BP]
    const float* __restrict__ obs_var,      // [K, BP, D]
    const float* __restrict__ hid_var,      // [K, BP, H]
    const float* __restrict__ next_var,     // [K, BP, H]
    const float* __restrict__ rec_biases,   // [K, BP]
    float* __restrict__ out, int BP)
{
    // One problem per 32-thread CTA: resources release at problem granularity.
    __shared__ float At[16 * SA];   // A^T   (16 rows x 64 gaussians)
    __shared__ float Bt[17 * SA];   // [Bm|c]^T (17 rows x 64)
    __shared__ float sM[16 * 17];   // Gram M -> Cholesky L (col 16 = 1/diag)
    __shared__ float sX[17 * 17];   // N -> X = M^{-1} A^T [Bm|c], column-major

    const int lane = threadIdx.x;
    const int prob = blockIdx.x;
    if (prob >= BP) return;

    const float4 xi = *reinterpret_cast<const float4*>(input_i + (size_t)prob * PD);

    // ---- load rows into shared (lane owns gaussians g0=lane, g1=lane+32) ----
    {
        float b0[16], b1[16], c0, c1;
        if (lane < PH) {
            const float4* p = reinterpret_cast<const float4*>(
                Prev_coefs + ((size_t)lane * BP + prob) * PH);
#pragma unroll
            for (int q = 0; q < 4; q++) {
                float4 v = p[q];
                At[(4*q+0)*SA + lane] = v.x; At[(4*q+1)*SA + lane] = v.y;
                At[(4*q+2)*SA + lane] = v.z; At[(4*q+3)*SA + lane] = v.w;
            }
#pragma unroll
            for (int i = 0; i < 16; i++) b0[i] = 0.0f;
            c0 = Prev_biases[(size_t)lane * BP + prob];
        } else {
            int k = lane - PH;
            const float4* p  = reinterpret_cast<const float4*>(
                hid_var + ((size_t)k * BP + prob) * PH);
            const float4* q4 = reinterpret_cast<const float4*>(
                next_var + ((size_t)k * BP + prob) * PH);
#pragma unroll
            for (int q = 0; q < 4; q++) {
                float4 v = p[q];
                At[(4*q+0)*SA + lane] = v.x; At[(4*q+1)*SA + lane] = v.y;
                At[(4*q+2)*SA + lane] = v.z; At[(4*q+3)*SA + lane] = v.w;
                float4 w = q4[q];
                b0[4*q+0] = w.x; b0[4*q+1] = w.y; b0[4*q+2] = w.z; b0[4*q+3] = w.w;
            }
            const float4 ov = *reinterpret_cast<const float4*>(
                obs_var + ((size_t)k * BP + prob) * PD);
            c0 = rec_biases[(size_t)k * BP + prob]
               + ov.x*xi.x + ov.y*xi.y + ov.z*xi.z + ov.w*xi.w;
        }
        {
            int k = lane + (32 - PH);
            const float4* p  = reinterpret_cast<const float4*>(
                hid_var + ((size_t)k * BP + prob) * PH);
            const float4* q4 = reinterpret_cast<const float4*>(
                next_var + ((size_t)k * BP + prob) * PH);
#pragma unroll
            for (int q = 0; q < 4; q++) {
                float4 v = p[q];
                At[(4*q+0)*SA + lane + 32] = v.x; At[(4*q+1)*SA + lane + 32] = v.y;
                At[(4*q+2)*SA + lane + 32] = v.z; At[(4*q+3)*SA + lane + 32] = v.w;
                float4 w = q4[q];
                b1[4*q+0] = w.x; b1[4*q+1] = w.y; b1[4*q+2] = w.z; b1[4*q+3] = w.w;
            }
            const float4 ov = *reinterpret_cast<const float4*>(
                obs_var + ((size_t)k * BP + prob) * PD);
            c1 = rec_biases[(size_t)k * BP + prob]
               + ov.x*xi.x + ov.y*xi.y + ov.z*xi.z + ov.w*xi.w;
        }
#pragma unroll
        for (int i = 0; i < 16; i++) {
            Bt[i*SA + lane]      = b0[i];
            Bt[i*SA + lane + 32] = b1[i];
        }
        Bt[16*SA + lane]      = c0;
        Bt[16*SA + lane + 32] = c1;
    }
    __syncwarp();

    // ---- M = A^T A : 2x2 register tiles; 36 tiles over 8x8 pair grid ----
#pragma unroll
    for (int rep = 0; rep < 2; rep++) {
        int t = lane + 32 * rep;
        if (t < 36) {
            int ti = 0, tt = t;
            while (tt >= 8 - ti) { tt -= 8 - ti; ++ti; }
            int tj = ti + tt;
            int i0 = 2*ti, i1 = i0 + 1, j0 = 2*tj, j1 = j0 + 1;
            const float2* Pi0 = reinterpret_cast<const float2*>(At + i0*SA);
            const float2* Pi1 = reinterpret_cast<const float2*>(At + i1*SA);
            const float2* Pj0 = reinterpret_cast<const float2*>(At + j0*SA);
            const float2* Pj1 = reinterpret_cast<const float2*>(At + j1*SA);
            float s00 = 0.0f, s01 = 0.0f, s10 = 0.0f, s11 = 0.0f;
#pragma unroll
            for (int g = 0; g < 32; g++) {
                float2 u0 = Pi0[g], u1 = Pi1[g], w0 = Pj0[g], w1 = Pj1[g];
                s00 = fmaf(u0.x, w0.x, s00); s00 = fmaf(u0.y, w0.y, s00);
                s01 = fmaf(u0.x, w1.x, s01); s01 = fmaf(u0.y, w1.y, s01);
                s10 = fmaf(u1.x, w0.x, s10); s10 = fmaf(u1.y, w0.y, s10);
                s11 = fmaf(u1.x, w1.x, s11); s11 = fmaf(u1.y, w1.y, s11);
            }
            sM[i0*17 + j0] = s00; sM[j0*17 + i0] = s00;
            sM[i0*17 + j1] = s01; sM[j1*17 + i0] = s01;
            sM[i1*17 + j0] = s10; sM[j0*17 + i1] = s10;
            sM[i1*17 + j1] = s11; sM[j1*17 + i1] = s11;
        }
    }
    __syncwarp();

    // ==== ONE barrier-free region: N-Gram + bn2 (throughput) overlapped with
    //      the register Cholesky (latency chain). They are independent. ====

    // ---- N = A^T Bm : 2x2 tiles over (8 i-pairs) x (8 k-pairs), zero rows skipped ----
#pragma unroll
    for (int rep = 0; rep < 2; rep++) {
        int t = lane + 32 * rep;           // 0..63, uniform tile code
        int ti = t & 7, tk = t >> 3;
        int i0 = 2*ti, i1 = i0 + 1, k0 = 2*tk, k1 = k0 + 1;
        // Bm columns are zero on gaussians 0..15 -> sum over g in [16,64)
        const float2* Pi0 = reinterpret_cast<const float2*>(At + i0*SA + 16);
        const float2* Pi1 = reinterpret_cast<const float2*>(At + i1*SA + 16);
        const float2* Qk0 = reinterpret_cast<const float2*>(Bt + k0*SA + 16);
        const float2* Qk1 = reinterpret_cast<const float2*>(Bt + k1*SA + 16);
        float s00 = 0.0f, s01 = 0.0f, s10 = 0.0f, s11 = 0.0f;
#pragma unroll
        for (int g = 0; g < 24; g++) {
            float2 u0 = Pi0[g], u1 = Pi1[g], w0 = Qk0[g], w1 = Qk1[g];
            s00 = fmaf(u0.x, w0.x, s00); s00 = fmaf(u0.y, w0.y, s00);
            s01 = fmaf(u0.x, w1.x, s01); s01 = fmaf(u0.y, w1.y, s01);
            s10 = fmaf(u1.x, w0.x, s10); s10 = fmaf(u1.y, w0.y, s10);
            s11 = fmaf(u1.x, w1.x, s11); s11 = fmaf(u1.y, w1.y, s11);
        }
        sX[k0*17 + i0] = s00; sX[k1*17 + i0] = s01;
        sX[k0*17 + i1] = s10; sX[k1*17 + i1] = s11;
    }
    // bias column k = 16 (full 64 gaussians): lanes 0..7, i-pair per lane
    if (lane < 8) {
        int i0 = 2*lane, i1 = i0 + 1;
        const float2* Pi0 = reinterpret_cast<const float2*>(At + i0*SA);
        const float2* Pi1 = reinterpret_cast<const float2*>(At + i1*SA);
        const float2* Qc  = reinterpret_cast<const float2*>(Bt + 16*SA);
        float s0 = 0.0f, s1 = 0.0f;
#pragma unroll
        for (int g = 0; g < 32; g++) {
            float2 u0 = Pi0[g], u1 = Pi1[g], w = Qc[g];
            s0 = fmaf(u0.x, w.x, s0); s0 = fmaf(u0.y, w.y, s0);
            s1 = fmaf(u1.x, w.x, s1); s1 = fmaf(u1.y, w.y, s1);
        }
        sX[16*17 + i0] = s0;
        sX[16*17 + i1] = s1;
    }

    // ---- column norms of [Bm|c] : lane k<17 owns column k ----
    float bn2 = 0.0f;
    if (lane < 17) bn2 = dot64(Bt + lane*SA, Bt + lane*SA);

    // ---- right-looking register Cholesky: lane i owns row i of M ----
    // rsqrt-based: no sqrt/div on the chain; lc1 term = -0.5*log(d_j).
    float neglog = 0.0f;
    {
        float m[16];
        int li = lane & 15;
#pragma unroll
        for (int k = 0; k < 16; k++) m[k] = sM[li*17 + k];

#pragma unroll
        for (int j = 0; j < 16; j++) {
            float d   = __shfl_sync(0xffffffffu, m[j], j);
            float rL  = rsqrtf(d);
            float lij = m[j] * rL;           // L_ij on lane i (valid for i > j)
            if (lane == j) {
                neglog = -0.5f * __logf(d);  // == -log(sqrt(d))
                sM[j*17 + 16] = rL;          // reciprocal diag for the solve
            } else if (lane > j && lane < 16) {
                sM[lane*17 + j] = lij;       // spill column j of L
            }
#pragma unroll
            for (int k = j + 1; k < 16; k++) {
                float lkj = __shfl_sync(0xffffffffu, lij, k);
                m[k] = fmaf(-lij, lkj, m[k]);
            }
        }
    }
    __syncwarp();

    // ---- solve M X = N per column (lane k<17); s_own = ||P col_k||^2 via qn ----
    float s_own = 0.0f;
    if (lane < 17) {
        float y[16];
#pragma unroll
        for (int i = 0; i < 16; i++) y[i] = sX[lane*17 + i];
        // forward: y := L^{-1} N_k  (parity-split partial sums)
#pragma unroll
        for (int i = 0; i < 16; i++) {
            float p0 = 0.0f, p1 = 0.0f;
#pragma unroll
            for (int t = 0; t < i; t++) {
                if (t & 1) p1 = fmaf(sM[i*17 + t], y[t], p1);
                else       p0 = fmaf(sM[i*17 + t], y[t], p0);
            }
            y[i] = (y[i] - (p0 + p1)) * sM[i*17 + 16];
        }
        float qn = 0.0f;
#pragma unroll
        for (int i = 0; i < 16; i++) qn = fmaf(y[i], y[i], qn);
        s_own = bn2 - qn;       // ||(I - Q1 Q1^T) col_k||^2
        // backward: y := L^{-T} y
#pragma unroll
        for (int i = 15; i >= 0; i--) {
            float p0 = 0.0f, p1 = 0.0f;
#pragma unroll
            for (int t = 15; t > i; t--) {
                if (t & 1) p1 = fmaf(sM[t*17 + i], y[t], p1);
                else       p0 = fmaf(sM[t*17 + i], y[t], p0);
            }
            y[i] = (y[i] - (p0 + p1)) * sM[i*17 + 16];
        }
#pragma unroll
        for (int i = 0; i < 16; i++) sX[lane*17 + i] = y[i];
    }
    __syncwarp();

    // ---- projection: PB = Bm - A X, Pc = c - A x_c (back into registers) ----
    float b0[16], b1[16], c0, c1;
#pragma unroll
    for (int i = 0; i < 16; i++) {
        b0[i] = Bt[i*SA + lane];
        b1[i] = Bt[i*SA + lane + 32];
    }
    c0 = Bt[16*SA + lane];
    c1 = Bt[16*SA + lane + 32];
#pragma unroll
    for (int i = 0; i < 16; i++) {
        float ai0 = At[i*SA + lane];
        float ai1 = At[i*SA + lane + 32];
#pragma unroll
        for (int k = 0; k < 16; k++) {
            float xv = sX[k*17 + i];
            b0[k] = fmaf(-ai0, xv, b0[k]);
            b1[k] = fmaf(-ai1, xv, b1[k]);
        }
        float xc = sX[16*17 + i];
        c0 = fmaf(-ai0, xc, c0);
        c1 = fmaf(-ai1, xc, c1);
    }

    float pc2 = __shfl_sync(0xffffffffu, s_own, 16);   // ||Pc||^2

    // ---- Householder QR on PB (slarfg convention), norms downdated ----
    // Pairs of trailing columns (warp_sum2). R_{j,k} recovered as bjk - w via a
    // prefetched shfl issued in parallel with the butterfly (bit-identical to
    // post-update shfl since v_j = 1), keeping the s_own downdate off the chain.
#pragma unroll
    for (int j = 0; j < 16; j++) {
        float sj    = __shfl_sync(0xffffffffu, s_own, j);   // ||col j rows>=j||^2
        float alpha = __shfl_sync(0xffffffffu, b0[j], j);
        sj = fmaxf(sj, 1e-30f);
        float beta = -copysignf(sqrtf(sj), alpha);
        float tau  = __fdividef(beta - alpha, beta);
        float inv  = __fdividef(1.0f, alpha - beta);

        float v0 = (lane == j) ? 1.0f : ((lane > j) ? b0[j] * inv : 0.0f);
        float v1 = b1[j] * inv;

        if (lane == j)      b0[j] = beta;
        else if (lane > j)  b0[j] = 0.0f;
        b1[j] = 0.0f;

        float xc = fmaf(v0, c0, v1 * c1);       // bias-column partial (off-chain)

        int k = j + 1;
#pragma unroll
        for (; k + 1 < 16; k += 2) {
            float bja = __shfl_sync(0xffffffffu, b0[k],   j);  // pre-update row-j vals
            float bjb = __shfl_sync(0xffffffffu, b0[k+1], j);
            float xa = fmaf(v0, b0[k],   v1 * b1[k]);
            float xb = fmaf(v0, b0[k+1], v1 * b1[k+1]);
            warp_sum2(xa, xb);
            float wa = tau * xa, wb = tau * xb;
            b0[k]   = fmaf(-wa, v0, b0[k]);   b1[k]   = fmaf(-wa, v1, b1[k]);
            b0[k+1] = fmaf(-wb, v0, b0[k+1]); b1[k+1] = fmaf(-wb, v1, b1[k+1]);
            float ra = bja - wa;              // == R_{j,k}   (v_j = 1)
            float rb = bjb - wb;              // == R_{j,k+1}
            if (lane == k)   s_own = fmaf(-ra, ra, s_own);
            if (lane == k+1) s_own = fmaf(-rb, rb, s_own);
        }
        if (k < 16) {
            // last odd trailing column paired with the bias column
            float bja = __shfl_sync(0xffffffffu, b0[k], j);
            float xa = fmaf(v0, b0[k], v1 * b1[k]);
            warp_sum2(xa, xc);
            float wa = tau * xa, wc = tau * xc;
            b0[k] = fmaf(-wa, v0, b0[k]);  b1[k] = fmaf(-wa, v1, b1[k]);
            c0 = fmaf(-wc, v0, c0);        c1 = fmaf(-wc, v1, c1);
            float ra = bja - wa;
            if (lane == k) s_own = fmaf(-ra, ra, s_own);
        } else {
            float wc = tau * warp_sum(xc);
            c0 = fmaf(-wc, v0, c0);
            c1 = fmaf(-wc, v1, c1);
        }
    }

    // final reductions fused: lc1 and nb2 in one pass
    float lc1 = neglog;
    float nb2 = (lane < 16) ? c0 * c0 : 0.0f;
    warp_sum2(lc1, nb2);
    float resid = fmaxf(pc2 - nb2, 0.0f);
    float LC = lc1 - 0.5f * ((float)(PK - PH) * LOG2PI + resid);

    // ---- outputs: Next_coefs [H,BP,H] | Next_biases [H,BP] | LP_new [BP] ----
    const size_t off1 = (size_t)PH * BP * PH;
    const size_t off2 = off1 + (size_t)PH * BP;

    if (lane < 16) {
        float4* po = reinterpret_cast<float4*>(out + ((size_t)lane * BP + prob) * PH);
        po[0] = make_float4(b0[0],  b0[1],  b0[2],  b0[3]);
        po[1] = make_float4(b0[4],  b0[5],  b0[6],  b0[7]);
        po[2] = make_float4(b0[8],  b0[9],  b0[10], b0[11]);
        po[3] = make_float4(b0[12], b0[13], b0[14], b0[15]);
        out[off1 + (size_t)lane * BP + prob] = c0;
    }
    if (lane == 0) {
        out[off2 + prob] = LP[prob] + LC + Log_factors[prob];
    }
}

extern "C" void kernel_launch(void* const* d_in, const int* in_sizes, int n_in,
                              void* d_out, int out_size) {
    const float* input_i     = (const float*)d_in[0];
    const float* Prev_coefs  = (const float*)d_in[1];
    const float* Prev_biases = (const float*)d_in[2];
    const float* LP          = (const float*)d_in[3];
    const float* Log_factors = (const float*)d_in[4];
    const float* obs_var     = (const float*)d_in[5];
    const float* hid_var     = (const float*)d_in[6];
    const float* next_var    = (const float*)d_in[7];
    const float* rec_biases  = (const float*)d_in[8];

    int BP = in_sizes[3];                     // B * P (size of LP)
    integ_kernel<<<BP, 32>>>(input_i, Prev_coefs, Prev_biases, LP, Log_factors,
                             obs_var, hid_var, next_var, rec_biases,
                             (float*)d_out, BP);
}

// round 14
// speedup vs baseline: 1.0399x; 1.0325x over previous
#include <cuda_runtime.h>
#include <math.h>

// Fixed shapes: B=2048, P=4, H=16, K=48, D=4, G=64
#define PH 16
#define PK 48
#define PD 4
#define LOG2PI 1.83787706640934548356f

#define SA 66              // shared row stride (floats): conflict-free
#define WPB 4              // warps (problems) per block

// unified per-warp smem layout (floats)
#define F_AT 0                       // A^T: 16 x SA
#define F_BT (16*SA)                 // [Bm|c]^T: 17 x SA          (=1056)
#define F_MM (F_BT + 17*SA)          // Gram M / Cholesky L: 16x17 (=2178)
#define F_XX (F_MM + 16*17)          // N -> X staging: 17x17      (=2450)
#define F_TOT 2756                   // X2 (dup -X, 289 u64) reuses [F_MM, F_MM+578)

typedef unsigned long long ull;

__device__ __forceinline__ ull fma2(ull a, ull b, ull c) {
    ull r;
    asm("fma.rn.f32x2 %0, %1, %2, %3;" : "=l"(r) : "l"(a), "l"(b), "l"(c));
    return r;
}
__device__ __forceinline__ ull pack2(float lo, float hi) {
    ull r;
    asm("mov.b64 %0, {%1, %2};" : "=l"(r) : "f"(lo), "f"(hi));
    return r;
}
__device__ __forceinline__ float2 unpack2(ull v) {
    float lo, hi;
    asm("mov.b64 {%0, %1}, %2;" : "=f"(lo), "=f"(hi) : "l"(v));
    return make_float2(lo, hi);
}
__device__ __forceinline__ float hadd2(ull v) { float2 f = unpack2(v); return f.x + f.y; }

__device__ __forceinline__ float warp_sum(float v) {
#pragma unroll
    for (int o = 16; o > 0; o >>= 1) v += __shfl_xor_sync(0xffffffffu, v, o);
    return v;
}
__device__ __forceinline__ void warp_sum2(float& a, float& b) {
#pragma unroll
    for (int o = 16; o > 0; o >>= 1) {
        float ta = __shfl_xor_sync(0xffffffffu, a, o);
        float tb = __shfl_xor_sync(0xffffffffu, b, o);
        a += ta; b += tb;
    }
}

// packed 64-length dot of two shared rows (8-byte aligned)
__device__ __forceinline__ float dot64(const float* p, const float* q) {
    const ull* P = reinterpret_cast<const ull*>(p);
    const ull* Q = reinterpret_cast<const ull*>(q);
    ull s0 = 0ull, s1 = 0ull;
#pragma unroll
    for (int g = 0; g < 32; g += 2) {
        s0 = fma2(P[g],   Q[g],   s0);
        s1 = fma2(P[g+1], Q[g+1], s1);
    }
    return hadd2(s0) + hadd2(s1);
}

__global__ __launch_bounds__(128, 5) void integ_kernel(
    const float* __restrict__ input_i,      // [BP, D]
    const float* __restrict__ Prev_coefs,   // [H, BP, H]
    const float* __restrict__ Prev_biases,  // [H, BP]
    const float* __restrict__ LP,           // [BP]
    const float* __restrict__ Log_factors,  // [BP]
    const float* __restrict__ obs_var,      // [K, BP, D]
    const float* __restrict__ hid_var,      // [K, BP, H]
    const float* __restrict__ next_var,     // [K, BP, H]
    const float* __restrict__ rec_biases,   // [K, BP]
    float* __restrict__ out, int BP)
{
    __shared__ float sbuf[WPB][F_TOT];

    const int warp = threadIdx.x >> 5;
    const int lane = threadIdx.x & 31;
    const int prob = blockIdx.x * WPB + warp;
    if (prob >= BP) return;

    float* At = sbuf[warp] + F_AT;
    float* Bt = sbuf[warp] + F_BT;
    float* sM = sbuf[warp] + F_MM;
    float* sX = sbuf[warp] + F_XX;
    ull*   X2 = reinterpret_cast<ull*>(sbuf[warp] + F_MM);  // reused AFTER solve

    const float4 xi = *reinterpret_cast<const float4*>(input_i + (size_t)prob * PD);

    // ---- load rows into shared (lane owns gaussians g0=lane, g1=lane+32) ----
    {
        float b0[16], b1[16], c0, c1;
        if (lane < PH) {
            const float4* p = reinterpret_cast<const float4*>(
                Prev_coefs + ((size_t)lane * BP + prob) * PH);
#pragma unroll
            for (int q = 0; q < 4; q++) {
                float4 v = p[q];
                At[(4*q+0)*SA + lane] = v.x; At[(4*q+1)*SA + lane] = v.y;
                At[(4*q+2)*SA + lane] = v.z; At[(4*q+3)*SA + lane] = v.w;
            }
#pragma unroll
            for (int i = 0; i < 16; i++) b0[i] = 0.0f;
            c0 = Prev_biases[(size_t)lane * BP + prob];
        } else {
            int k = lane - PH;
            const float4* p  = reinterpret_cast<const float4*>(
                hid_var + ((size_t)k * BP + prob) * PH);
            const float4* q4 = reinterpret_cast<const float4*>(
                next_var + ((size_t)k * BP + prob) * PH);
#pragma unroll
            for (int q = 0; q < 4; q++) {
                float4 v = p[q];
                At[(4*q+0)*SA + lane] = v.x; At[(4*q+1)*SA + lane] = v.y;
                At[(4*q+2)*SA + lane] = v.z; At[(4*q+3)*SA + lane] = v.w;
                float4 w = q4[q];
                b0[4*q+0] = w.x; b0[4*q+1] = w.y; b0[4*q+2] = w.z; b0[4*q+3] = w.w;
            }
            const float4 ov = *reinterpret_cast<const float4*>(
                obs_var + ((size_t)k * BP + prob) * PD);
            c0 = rec_biases[(size_t)k * BP + prob]
               + ov.x*xi.x + ov.y*xi.y + ov.z*xi.z + ov.w*xi.w;
        }
        {
            int k = lane + (32 - PH);
            const float4* p  = reinterpret_cast<const float4*>(
                hid_var + ((size_t)k * BP + prob) * PH);
            const float4* q4 = reinterpret_cast<const float4*>(
                next_var + ((size_t)k * BP + prob) * PH);
#pragma unroll
            for (int q = 0; q < 4; q++) {
                float4 v = p[q];
                At[(4*q+0)*SA + lane + 32] = v.x; At[(4*q+1)*SA + lane + 32] = v.y;
                At[(4*q+2)*SA + lane + 32] = v.z; At[(4*q+3)*SA + lane + 32] = v.w;
                float4 w = q4[q];
                b1[4*q+0] = w.x; b1[4*q+1] = w.y; b1[4*q+2] = w.z; b1[4*q+3] = w.w;
            }
            const float4 ov = *reinterpret_cast<const float4*>(
                obs_var + ((size_t)k * BP + prob) * PD);
            c1 = rec_biases[(size_t)k * BP + prob]
               + ov.x*xi.x + ov.y*xi.y + ov.z*xi.z + ov.w*xi.w;
        }
#pragma unroll
        for (int i = 0; i < 16; i++) {
            Bt[i*SA + lane]      = b0[i];
            Bt[i*SA + lane + 32] = b1[i];
        }
        Bt[16*SA + lane]      = c0;
        Bt[16*SA + lane + 32] = c1;
    }
    __syncwarp();

    // ---- M = A^T A : 2x2 register tiles, packed f32x2 FMAs ----
#pragma unroll
    for (int rep = 0; rep < 2; rep++) {
        int t = lane + 32 * rep;
        if (t < 36) {
            int ti = 0, tt = t;
            while (tt >= 8 - ti) { tt -= 8 - ti; ++ti; }
            int tj = ti + tt;
            int i0 = 2*ti, i1 = i0 + 1, j0 = 2*tj, j1 = j0 + 1;
            const ull* Pi0 = reinterpret_cast<const ull*>(At + i0*SA);
            const ull* Pi1 = reinterpret_cast<const ull*>(At + i1*SA);
            const ull* Pj0 = reinterpret_cast<const ull*>(At + j0*SA);
            const ull* Pj1 = reinterpret_cast<const ull*>(At + j1*SA);
            ull s00 = 0ull, s01 = 0ull, s10 = 0ull, s11 = 0ull;
#pragma unroll
            for (int g = 0; g < 32; g++) {
                ull u0 = Pi0[g], u1 = Pi1[g], w0 = Pj0[g], w1 = Pj1[g];
                s00 = fma2(u0, w0, s00);
                s01 = fma2(u0, w1, s01);
                s10 = fma2(u1, w0, s10);
                s11 = fma2(u1, w1, s11);
            }
            float f00 = hadd2(s00), f01 = hadd2(s01), f10 = hadd2(s10), f11 = hadd2(s11);
            sM[i0*17 + j0] = f00; sM[j0*17 + i0] = f00;
            sM[i0*17 + j1] = f01; sM[j1*17 + i0] = f01;
            sM[i1*17 + j0] = f10; sM[j0*17 + i1] = f10;
            sM[i1*17 + j1] = f11; sM[j1*17 + i1] = f11;
        }
    }
    __syncwarp();

    // ==== barrier-free region: N-Gram + bn2 overlapped with register Cholesky ====

    // ---- N = A^T Bm : 2x2 tiles, packed; Bm zero rows (g<16) skipped ----
#pragma unroll
    for (int rep = 0; rep < 2; rep++) {
        int t = lane + 32 * rep;
        int ti = t & 7, tk = t >> 3;
        int i0 = 2*ti, i1 = i0 + 1, k0 = 2*tk, k1 = k0 + 1;
        const ull* Pi0 = reinterpret_cast<const ull*>(At + i0*SA + 16);
        const ull* Pi1 = reinterpret_cast<const ull*>(At + i1*SA + 16);
        const ull* Qk0 = reinterpret_cast<const ull*>(Bt + k0*SA + 16);
        const ull* Qk1 = reinterpret_cast<const ull*>(Bt + k1*SA + 16);
        ull s00 = 0ull, s01 = 0ull, s10 = 0ull, s11 = 0ull;
#pragma unroll
        for (int g = 0; g < 24; g++) {
            ull u0 = Pi0[g], u1 = Pi1[g], w0 = Qk0[g], w1 = Qk1[g];
            s00 = fma2(u0, w0, s00);
            s01 = fma2(u0, w1, s01);
            s10 = fma2(u1, w0, s10);
            s11 = fma2(u1, w1, s11);
        }
        sX[k0*17 + i0] = hadd2(s00); sX[k1*17 + i0] = hadd2(s01);
        sX[k0*17 + i1] = hadd2(s10); sX[k1*17 + i1] = hadd2(s11);
    }
    // bias column k = 16 (full 64 gaussians): lanes 0..7
    if (lane < 8) {
        int i0 = 2*lane, i1 = i0 + 1;
        const ull* Pi0 = reinterpret_cast<const ull*>(At + i0*SA);
        const ull* Pi1 = reinterpret_cast<const ull*>(At + i1*SA);
        const ull* Qc  = reinterpret_cast<const ull*>(Bt + 16*SA);
        ull s0 = 0ull, s1 = 0ull;
#pragma unroll
        for (int g = 0; g < 32; g++) {
            ull u0 = Pi0[g], u1 = Pi1[g], w = Qc[g];
            s0 = fma2(u0, w, s0);
            s1 = fma2(u1, w, s1);
        }
        sX[16*17 + i0] = hadd2(s0);
        sX[16*17 + i1] = hadd2(s1);
    }

    // ---- column norms of [Bm|c] : lane k<17 owns column k ----
    float bn2 = 0.0f;
    if (lane < 17) bn2 = dot64(Bt + lane*SA, Bt + lane*SA);

    // ---- right-looking register Cholesky (rsqrt, no barriers inside) ----
    float neglog = 0.0f;
    {
        float m[16];
        int li = lane & 15;
#pragma unroll
        for (int k = 0; k < 16; k++) m[k] = sM[li*17 + k];

#pragma unroll
        for (int j = 0; j < 16; j++) {
            float d   = __shfl_sync(0xffffffffu, m[j], j);
            float rL  = rsqrtf(d);
            float lij = m[j] * rL;
            if (lane == j) {
                neglog = -0.5f * __logf(d);
                sM[j*17 + 16] = rL;
            } else if (lane > j && lane < 16) {
                sM[lane*17 + j] = lij;
            }
#pragma unroll
            for (int k = j + 1; k < 16; k++) {
                float lkj = __shfl_sync(0xffffffffu, lij, k);
                m[k] = fmaf(-lij, lkj, m[k]);
            }
        }
    }
    __syncwarp();

    // ---- solve M X = N per column (lane k<17); y stays in registers ----
    float s_own = 0.0f;
    float y[16];
    if (lane < 17) {
#pragma unroll
        for (int i = 0; i < 16; i++) y[i] = sX[lane*17 + i];
#pragma unroll
        for (int i = 0; i < 16; i++) {
            float p0 = 0.0f, p1 = 0.0f;
#pragma unroll
            for (int t = 0; t < i; t++) {
                if (t & 1) p1 = fmaf(sM[i*17 + t], y[t], p1);
                else       p0 = fmaf(sM[i*17 + t], y[t], p0);
            }
            y[i] = (y[i] - (p0 + p1)) * sM[i*17 + 16];
        }
        float qn = 0.0f;
#pragma unroll
        for (int i = 0; i < 16; i++) qn = fmaf(y[i], y[i], qn);
        s_own = bn2 - qn;
#pragma unroll
        for (int i = 15; i >= 0; i--) {
            float p0 = 0.0f, p1 = 0.0f;
#pragma unroll
            for (int t = 15; t > i; t--) {
                if (t & 1) p1 = fmaf(sM[t*17 + i], y[t], p1);
                else       p0 = fmaf(sM[t*17 + i], y[t], p0);
            }
            y[i] = (y[i] - (p0 + p1)) * sM[i*17 + 16];
        }
    }
    __syncwarp();   // all sM/sX reads done before X2 overwrites the region

    // write duplicated NEGATED X into the dead sM/sX region (one STS.64 each)
    if (lane < 17) {
#pragma unroll
        for (int i = 0; i < 16; i++) X2[lane*17 + i] = pack2(-y[i], -y[i]);
    }
    __syncwarp();

    // ---- projection: PB = Bm - A X (packed rows), Pc = c - A x_c ----
    ull bk[16], cc;
#pragma unroll
    for (int k = 0; k < 16; k++) bk[k] = pack2(Bt[k*SA + lane], Bt[k*SA + lane + 32]);
    cc = pack2(Bt[16*SA + lane], Bt[16*SA + lane + 32]);
#pragma unroll
    for (int i = 0; i < 16; i++) {
        ull ai = pack2(At[i*SA + lane], At[i*SA + lane + 32]);
#pragma unroll
        for (int k = 0; k < 16; k++) {
            bk[k] = fma2(ai, X2[k*17 + i], bk[k]);   // X2 holds -X, broadcast LDS.64
        }
        cc = fma2(ai, X2[16*17 + i], cc);
    }

    float b0[16], b1[16], c0, c1;
#pragma unroll
    for (int k = 0; k < 16; k++) {
        float2 f = unpack2(bk[k]);
        b0[k] = f.x; b1[k] = f.y;
    }
    { float2 f = unpack2(cc); c0 = f.x; c1 = f.y; }

    float pc2 = __shfl_sync(0xffffffffu, s_own, 16);   // ||Pc||^2

    // ---- Householder QR on PB (slarfg convention), norms downdated ----
#pragma unroll
    for (int j = 0; j < 16; j++) {
        float sj    = __shfl_sync(0xffffffffu, s_own, j);
        float alpha = __shfl_sync(0xffffffffu, b0[j], j);
        sj = fmaxf(sj, 1e-30f);
        float beta = -copysignf(sqrtf(sj), alpha);
        float tau  = __fdividef(beta - alpha, beta);
        float inv  = __fdividef(1.0f, alpha - beta);

        float v0 = (lane == j) ? 1.0f : ((lane > j) ? b0[j] * inv : 0.0f);
        float v1 = b1[j] * inv;

        if (lane == j)      b0[j] = beta;
        else if (lane > j)  b0[j] = 0.0f;
        b1[j] = 0.0f;

        float xc = fmaf(v0, c0, v1 * c1);

        int k = j + 1;
#pragma unroll
        for (; k + 1 < 16; k += 2) {
            float bja = __shfl_sync(0xffffffffu, b0[k],   j);
            float bjb = __shfl_sync(0xffffffffu, b0[k+1], j);
            float xa = fmaf(v0, b0[k],   v1 * b1[k]);
            float xb = fmaf(v0, b0[k+1], v1 * b1[k+1]);
            warp_sum2(xa, xb);
            float wa = tau * xa, wb = tau * xb;
            b0[k]   = fmaf(-wa, v0, b0[k]);   b1[k]   = fmaf(-wa, v1, b1[k]);
            b0[k+1] = fmaf(-wb, v0, b0[k+1]); b1[k+1] = fmaf(-wb, v1, b1[k+1]);
            float ra = bja - wa;
            float rb = bjb - wb;
            if (lane == k)   s_own = fmaf(-ra, ra, s_own);
            if (lane == k+1) s_own = fmaf(-rb, rb, s_own);
        }
        if (k < 16) {
            float bja = __shfl_sync(0xffffffffu, b0[k], j);
            float xa = fmaf(v0, b0[k], v1 * b1[k]);
            warp_sum2(xa, xc);
            float wa = tau * xa, wc = tau * xc;
            b0[k] = fmaf(-wa, v0, b0[k]);  b1[k] = fmaf(-wa, v1, b1[k]);
            c0 = fmaf(-wc, v0, c0);        c1 = fmaf(-wc, v1, c1);
            float ra = bja - wa;
            if (lane == k) s_own = fmaf(-ra, ra, s_own);
        } else {
            float wc = tau * warp_sum(xc);
            c0 = fmaf(-wc, v0, c0);
            c1 = fmaf(-wc, v1, c1);
        }
    }

    // final reductions fused
    float lc1 = neglog;
    float nb2 = (lane < 16) ? c0 * c0 : 0.0f;
    warp_sum2(lc1, nb2);
    float resid = fmaxf(pc2 - nb2, 0.0f);
    float LC = lc1 - 0.5f * ((float)(PK - PH) * LOG2PI + resid);

    // ---- outputs: Next_coefs [H,BP,H] | Next_biases [H,BP] | LP_new [BP] ----
    const size_t off1 = (size_t)PH * BP * PH;
    const size_t off2 = off1 + (size_t)PH * BP;

    if (lane < 16) {
        float4* po = reinterpret_cast<float4*>(out + ((size_t)lane * BP + prob) * PH);
        po[0] = make_float4(b0[0],  b0[1],  b0[2],  b0[3]);
        po[1] = make_float4(b0[4],  b0[5],  b0[6],  b0[7]);
        po[2] = make_float4(b0[8],  b0[9],  b0[10], b0[11]);
        po[3] = make_float4(b0[12], b0[13], b0[14], b0[15]);
        out[off1 + (size_t)lane * BP + prob] = c0;
    }
    if (lane == 0) {
        out[off2 + prob] = LP[prob] + LC + Log_factors[prob];
    }
}

extern "C" void kernel_launch(void* const* d_in, const int* in_sizes, int n_in,
                              void* d_out, int out_size) {
    const float* input_i     = (const float*)d_in[0];
    const float* Prev_coefs  = (const float*)d_in[1];
    const float* Prev_biases = (const float*)d_in[2];
    const float* LP          = (const float*)d_in[3];
    const float* Log_factors = (const float*)d_in[4];
    const float* obs_var     = (const float*)d_in[5];
    const float* hid_var     = (const float*)d_in[6];
    const float* next_var    = (const float*)d_in[7];
    const float* rec_biases  = (const float*)d_in[8];

    int BP = in_sizes[3];                     // B * P (size of LP)
    int blocks = (BP + WPB - 1) / WPB;        // 1 problem per warp, 4 warps/block
    integ_kernel<<<blocks, WPB * 32>>>(input_i, Prev_coefs, Prev_biases, LP, Log_factors,
                                       obs_var, hid_var, next_var, rec_biases,
                                       (float*)d_out, BP);
}

// round 15
// speedup vs baseline: 1.1169x; 1.0740x over previous
#include <cuda_runtime.h>
#include <math.h>

// Fixed shapes: B=2048, P=4, H=16, K=48, D=4, G=64
#define PH 16
#define PK 48
#define PD 4
#define LOG2PI 1.83787706640934548356f

#define SA 66              // shared row stride (floats): conflict-free
#define WPB 4              // warps (problems) per block

// unified per-warp smem layout (floats)
#define F_AT 0                       // A^T: 16 x SA
#define F_BT (16*SA)                 // [Bm|c]^T: 17 x SA          (=1056)
#define F_MM (F_BT + 17*SA)          // Gram M / Cholesky L: 16x17 (=2178)
#define F_XX (F_MM + 16*17)          // N -> X staging: 17x17      (=2450)
#define F_TOT 2756                   // X2 (dup -X, 289 u64) reuses [F_MM, F_MM+578)

typedef unsigned long long ull;

__device__ __forceinline__ ull fma2(ull a, ull b, ull c) {
    ull r;
    asm("fma.rn.f32x2 %0, %1, %2, %3;" : "=l"(r) : "l"(a), "l"(b), "l"(c));
    return r;
}
__device__ __forceinline__ ull pack2(float lo, float hi) {
    ull r;
    asm("mov.b64 %0, {%1, %2};" : "=l"(r) : "f"(lo), "f"(hi));
    return r;
}
__device__ __forceinline__ float2 unpack2(ull v) {
    float lo, hi;
    asm("mov.b64 {%0, %1}, %2;" : "=f"(lo), "=f"(hi) : "l"(v));
    return make_float2(lo, hi);
}
__device__ __forceinline__ float hadd2(ull v) { float2 f = unpack2(v); return f.x + f.y; }

__device__ __forceinline__ float warp_sum(float v) {
#pragma unroll
    for (int o = 16; o > 0; o >>= 1) v += __shfl_xor_sync(0xffffffffu, v, o);
    return v;
}
__device__ __forceinline__ void warp_sum2(float& a, float& b) {
#pragma unroll
    for (int o = 16; o > 0; o >>= 1) {
        float ta = __shfl_xor_sync(0xffffffffu, a, o);
        float tb = __shfl_xor_sync(0xffffffffu, b, o);
        a += ta; b += tb;
    }
}

// packed 64-length dot of two shared rows (8-byte aligned)
__device__ __forceinline__ float dot64(const float* p, const float* q) {
    const ull* P = reinterpret_cast<const ull*>(p);
    const ull* Q = reinterpret_cast<const ull*>(q);
    ull s0 = 0ull, s1 = 0ull;
#pragma unroll
    for (int g = 0; g < 32; g += 2) {
        s0 = fma2(P[g],   Q[g],   s0);
        s1 = fma2(P[g+1], Q[g+1], s1);
    }
    return hadd2(s0) + hadd2(s1);
}

__global__ __launch_bounds__(128, 4) void integ_kernel(
    const float* __restrict__ input_i,      // [BP, D]
    const float* __restrict__ Prev_coefs,   // [H, BP, H]
    const float* __restrict__ Prev_biases,  // [H, BP]
    const float* __restrict__ LP,           // [BP]
    const float* __restrict__ Log_factors,  // [BP]
    const float* __restrict__ obs_var,      // [K, BP, D]
    const float* __restrict__ hid_var,      // [K, BP, H]
    const float* __restrict__ next_var,     // [K, BP, H]
    const float* __restrict__ rec_biases,   // [K, BP]
    float* __restrict__ out, int BP)
{
    __shared__ float sbuf[WPB][F_TOT];

    const int warp = threadIdx.x >> 5;
    const int lane = threadIdx.x & 31;
    const int prob = blockIdx.x * WPB + warp;
    if (prob >= BP) return;

    float* At = sbuf[warp] + F_AT;
    float* Bt = sbuf[warp] + F_BT;
    float* sM = sbuf[warp] + F_MM;
    float* sX = sbuf[warp] + F_XX;
    ull*   X2 = reinterpret_cast<ull*>(sbuf[warp] + F_MM);  // reused AFTER solve

    const float4 xi = *reinterpret_cast<const float4*>(input_i + (size_t)prob * PD);

    // ---- load rows into shared (lane owns gaussians g0=lane, g1=lane+32) ----
    {
        float b0[16], b1[16], c0, c1;
        if (lane < PH) {
            const float4* p = reinterpret_cast<const float4*>(
                Prev_coefs + ((size_t)lane * BP + prob) * PH);
#pragma unroll
            for (int q = 0; q < 4; q++) {
                float4 v = p[q];
                At[(4*q+0)*SA + lane] = v.x; At[(4*q+1)*SA + lane] = v.y;
                At[(4*q+2)*SA + lane] = v.z; At[(4*q+3)*SA + lane] = v.w;
            }
#pragma unroll
            for (int i = 0; i < 16; i++) b0[i] = 0.0f;
            c0 = Prev_biases[(size_t)lane * BP + prob];
        } else {
            int k = lane - PH;
            const float4* p  = reinterpret_cast<const float4*>(
                hid_var + ((size_t)k * BP + prob) * PH);
            const float4* q4 = reinterpret_cast<const float4*>(
                next_var + ((size_t)k * BP + prob) * PH);
#pragma unroll
            for (int q = 0; q < 4; q++) {
                float4 v = p[q];
                At[(4*q+0)*SA + lane] = v.x; At[(4*q+1)*SA + lane] = v.y;
                At[(4*q+2)*SA + lane] = v.z; At[(4*q+3)*SA + lane] = v.w;
                float4 w = q4[q];
                b0[4*q+0] = w.x; b0[4*q+1] = w.y; b0[4*q+2] = w.z; b0[4*q+3] = w.w;
            }
            const float4 ov = *reinterpret_cast<const float4*>(
                obs_var + ((size_t)k * BP + prob) * PD);
            c0 = rec_biases[(size_t)k * BP + prob]
               + ov.x*xi.x + ov.y*xi.y + ov.z*xi.z + ov.w*xi.w;
        }
        {
            int k = lane + (32 - PH);
            const float4* p  = reinterpret_cast<const float4*>(
                hid_var + ((size_t)k * BP + prob) * PH);
            const float4* q4 = reinterpret_cast<const float4*>(
                next_var + ((size_t)k * BP + prob) * PH);
#pragma unroll
            for (int q = 0; q < 4; q++) {
                float4 v = p[q];
                At[(4*q+0)*SA + lane + 32] = v.x; At[(4*q+1)*SA + lane + 32] = v.y;
                At[(4*q+2)*SA + lane + 32] = v.z; At[(4*q+3)*SA + lane + 32] = v.w;
                float4 w = q4[q];
                b1[4*q+0] = w.x; b1[4*q+1] = w.y; b1[4*q+2] = w.z; b1[4*q+3] = w.w;
            }
            const float4 ov = *reinterpret_cast<const float4*>(
                obs_var + ((size_t)k * BP + prob) * PD);
            c1 = rec_biases[(size_t)k * BP + prob]
               + ov.x*xi.x + ov.y*xi.y + ov.z*xi.z + ov.w*xi.w;
        }
#pragma unroll
        for (int i = 0; i < 16; i++) {
            Bt[i*SA + lane]      = b0[i];
            Bt[i*SA + lane + 32] = b1[i];
        }
        Bt[16*SA + lane]      = c0;
        Bt[16*SA + lane + 32] = c1;
    }
    __syncwarp();

    // ---- M = A^T A : 2x2 register tiles, packed f32x2 FMAs ----
#pragma unroll
    for (int rep = 0; rep < 2; rep++) {
        int t = lane + 32 * rep;
        if (t < 36) {
            int ti = 0, tt = t;
            while (tt >= 8 - ti) { tt -= 8 - ti; ++ti; }
            int tj = ti + tt;
            int i0 = 2*ti, i1 = i0 + 1, j0 = 2*tj, j1 = j0 + 1;
            const ull* Pi0 = reinterpret_cast<const ull*>(At + i0*SA);
            const ull* Pi1 = reinterpret_cast<const ull*>(At + i1*SA);
            const ull* Pj0 = reinterpret_cast<const ull*>(At + j0*SA);
            const ull* Pj1 = reinterpret_cast<const ull*>(At + j1*SA);
            ull s00 = 0ull, s01 = 0ull, s10 = 0ull, s11 = 0ull;
#pragma unroll
            for (int g = 0; g < 32; g++) {
                ull u0 = Pi0[g], u1 = Pi1[g], w0 = Pj0[g], w1 = Pj1[g];
                s00 = fma2(u0, w0, s00);
                s01 = fma2(u0, w1, s01);
                s10 = fma2(u1, w0, s10);
                s11 = fma2(u1, w1, s11);
            }
            float f00 = hadd2(s00), f01 = hadd2(s01), f10 = hadd2(s10), f11 = hadd2(s11);
            sM[i0*17 + j0] = f00; sM[j0*17 + i0] = f00;
            sM[i0*17 + j1] = f01; sM[j1*17 + i0] = f01;
            sM[i1*17 + j0] = f10; sM[j0*17 + i1] = f10;
            sM[i1*17 + j1] = f11; sM[j1*17 + i1] = f11;
        }
    }
    __syncwarp();

    // ==== barrier-free region: N-Gram + bn2 overlapped with register Cholesky ====

    // ---- N = A^T Bm : FUSED 2x4 tiles (lane owns i-pair ti and k-quads tk,tk+4);
    //      A rows loaded ONCE per g for both k-quads. Bm zero rows (g<16) skipped.
    {
        int ti = lane & 7, tk = lane >> 3;
        int i0 = 2*ti, i1 = i0 + 1;
        int kA0 = 2*tk,       kA1 = kA0 + 1;
        int kB0 = 2*(tk + 4), kB1 = kB0 + 1;
        const ull* Pi0 = reinterpret_cast<const ull*>(At + i0*SA + 16);
        const ull* Pi1 = reinterpret_cast<const ull*>(At + i1*SA + 16);
        const ull* QA0 = reinterpret_cast<const ull*>(Bt + kA0*SA + 16);
        const ull* QA1 = reinterpret_cast<const ull*>(Bt + kA1*SA + 16);
        const ull* QB0 = reinterpret_cast<const ull*>(Bt + kB0*SA + 16);
        const ull* QB1 = reinterpret_cast<const ull*>(Bt + kB1*SA + 16);
        ull sA00=0ull, sA01=0ull, sA10=0ull, sA11=0ull;
        ull sB00=0ull, sB01=0ull, sB10=0ull, sB11=0ull;
#pragma unroll
        for (int g = 0; g < 24; g++) {
            ull u0 = Pi0[g], u1 = Pi1[g];
            ull a0 = QA0[g], a1 = QA1[g], b0v = QB0[g], b1v = QB1[g];
            sA00 = fma2(u0, a0, sA00);
            sA01 = fma2(u0, a1, sA01);
            sA10 = fma2(u1, a0, sA10);
            sA11 = fma2(u1, a1, sA11);
            sB00 = fma2(u0, b0v, sB00);
            sB01 = fma2(u0, b1v, sB01);
            sB10 = fma2(u1, b0v, sB10);
            sB11 = fma2(u1, b1v, sB11);
        }
        sX[kA0*17 + i0] = hadd2(sA00); sX[kA1*17 + i0] = hadd2(sA01);
        sX[kA0*17 + i1] = hadd2(sA10); sX[kA1*17 + i1] = hadd2(sA11);
        sX[kB0*17 + i0] = hadd2(sB00); sX[kB1*17 + i0] = hadd2(sB01);
        sX[kB0*17 + i1] = hadd2(sB10); sX[kB1*17 + i1] = hadd2(sB11);
    }
    // bias column k = 16 (full 64 gaussians): lanes 0..7
    if (lane < 8) {
        int i0 = 2*lane, i1 = i0 + 1;
        const ull* Pi0 = reinterpret_cast<const ull*>(At + i0*SA);
        const ull* Pi1 = reinterpret_cast<const ull*>(At + i1*SA);
        const ull* Qc  = reinterpret_cast<const ull*>(Bt + 16*SA);
        ull s0 = 0ull, s1 = 0ull;
#pragma unroll
        for (int g = 0; g < 32; g++) {
            ull u0 = Pi0[g], u1 = Pi1[g], w = Qc[g];
            s0 = fma2(u0, w, s0);
            s1 = fma2(u1, w, s1);
        }
        sX[16*17 + i0] = hadd2(s0);
        sX[16*17 + i1] = hadd2(s1);
    }

    // ---- column norms of [Bm|c] : lane k<17 owns column k ----
    float bn2 = 0.0f;
    if (lane < 17) bn2 = dot64(Bt + lane*SA, Bt + lane*SA);

    // ---- right-looking register Cholesky (rsqrt, no barriers inside) ----
    float neglog = 0.0f;
    {
        float m[16];
        int li = lane & 15;
#pragma unroll
        for (int k = 0; k < 16; k++) m[k] = sM[li*17 + k];

#pragma unroll
        for (int j = 0; j < 16; j++) {
            float d   = __shfl_sync(0xffffffffu, m[j], j);
            float rL  = rsqrtf(d);
            float lij = m[j] * rL;
            if (lane == j) {
                neglog = -0.5f * __logf(d);
                sM[j*17 + 16] = rL;
            } else if (lane > j && lane < 16) {
                sM[lane*17 + j] = lij;
            }
#pragma unroll
            for (int k = j + 1; k < 16; k++) {
                float lkj = __shfl_sync(0xffffffffu, lij, k);
                m[k] = fmaf(-lij, lkj, m[k]);
            }
        }
    }
    __syncwarp();

    // ---- solve M X = N per column (lane k<17); y stays in registers ----
    float s_own = 0.0f;
    float y[16];
    if (lane < 17) {
#pragma unroll
        for (int i = 0; i < 16; i++) y[i] = sX[lane*17 + i];
#pragma unroll
        for (int i = 0; i < 16; i++) {
            float p0 = 0.0f, p1 = 0.0f;
#pragma unroll
            for (int t = 0; t < i; t++) {
                if (t & 1) p1 = fmaf(sM[i*17 + t], y[t], p1);
                else       p0 = fmaf(sM[i*17 + t], y[t], p0);
            }
            y[i] = (y[i] - (p0 + p1)) * sM[i*17 + 16];
        }
        float qn = 0.0f;
#pragma unroll
        for (int i = 0; i < 16; i++) qn = fmaf(y[i], y[i], qn);
        s_own = bn2 - qn;
#pragma unroll
        for (int i = 15; i >= 0; i--) {
            float p0 = 0.0f, p1 = 0.0f;
#pragma unroll
            for (int t = 15; t > i; t--) {
                if (t & 1) p1 = fmaf(sM[t*17 + i], y[t], p1);
                else       p0 = fmaf(sM[t*17 + i], y[t], p0);
            }
            y[i] = (y[i] - (p0 + p1)) * sM[i*17 + 16];
        }
    }
    __syncwarp();   // all sM/sX reads done before X2 overwrites the region

    // write duplicated NEGATED X into the dead sM/sX region (one STS.64 each)
    if (lane < 17) {
#pragma unroll
        for (int i = 0; i < 16; i++) X2[lane*17 + i] = pack2(-y[i], -y[i]);
    }
    __syncwarp();

    // ---- projection: PB = Bm - A X (packed rows), Pc = c - A x_c ----
    ull bk[16], cc;
#pragma unroll
    for (int k = 0; k < 16; k++) bk[k] = pack2(Bt[k*SA + lane], Bt[k*SA + lane + 32]);
    cc = pack2(Bt[16*SA + lane], Bt[16*SA + lane + 32]);
#pragma unroll
    for (int i = 0; i < 16; i++) {
        ull ai = pack2(At[i*SA + lane], At[i*SA + lane + 32]);
#pragma unroll
        for (int k = 0; k < 16; k++) {
            bk[k] = fma2(ai, X2[k*17 + i], bk[k]);   // X2 holds -X, broadcast LDS.64
        }
        cc = fma2(ai, X2[16*17 + i], cc);
    }

    float b0[16], b1[16], c0, c1;
#pragma unroll
    for (int k = 0; k < 16; k++) {
        float2 f = unpack2(bk[k]);
        b0[k] = f.x; b1[k] = f.y;
    }
    { float2 f = unpack2(cc); c0 = f.x; c1 = f.y; }

    float pc2 = __shfl_sync(0xffffffffu, s_own, 16);   // ||Pc||^2

    // ---- Householder QR on PB (slarfg convention), norms downdated ----
#pragma unroll
    for (int j = 0; j < 16; j++) {
        float sj    = __shfl_sync(0xffffffffu, s_own, j);
        float alpha = __shfl_sync(0xffffffffu, b0[j], j);
        sj = fmaxf(sj, 1e-30f);
        float beta = -copysignf(sqrtf(sj), alpha);
        float tau  = __fdividef(beta - alpha, beta);
        float inv  = __fdividef(1.0f, alpha - beta);

        float v0 = (lane == j) ? 1.0f : ((lane > j) ? b0[j] * inv : 0.0f);
        float v1 = b1[j] * inv;

        if (lane == j)      b0[j] = beta;
        else if (lane > j)  b0[j] = 0.0f;
        b1[j] = 0.0f;

        float xc = fmaf(v0, c0, v1 * c1);

        int k = j + 1;
#pragma unroll
        for (; k + 1 < 16; k += 2) {
            float bja = __shfl_sync(0xffffffffu, b0[k],   j);
            float bjb = __shfl_sync(0xffffffffu, b0[k+1], j);
            float xa = fmaf(v0, b0[k],   v1 * b1[k]);
            float xb = fmaf(v0, b0[k+1], v1 * b1[k+1]);
            warp_sum2(xa, xb);
            float wa = tau * xa, wb = tau * xb;
            b0[k]   = fmaf(-wa, v0, b0[k]);   b1[k]   = fmaf(-wa, v1, b1[k]);
            b0[k+1] = fmaf(-wb, v0, b0[k+1]); b1[k+1] = fmaf(-wb, v1, b1[k+1]);
            float ra = bja - wa;
            float rb = bjb - wb;
            if (lane == k)   s_own = fmaf(-ra, ra, s_own);
            if (lane == k+1) s_own = fmaf(-rb, rb, s_own);
        }
        if (k < 16) {
            float bja = __shfl_sync(0xffffffffu, b0[k], j);
            float xa = fmaf(v0, b0[k], v1 * b1[k]);
            warp_sum2(xa, xc);
            float wa = tau * xa, wc = tau * xc;
            b0[k] = fmaf(-wa, v0, b0[k]);  b1[k] = fmaf(-wa, v1, b1[k]);
            c0 = fmaf(-wc, v0, c0);        c1 = fmaf(-wc, v1, c1);
            float ra = bja - wa;
            if (lane == k) s_own = fmaf(-ra, ra, s_own);
        } else {
            float wc = tau * warp_sum(xc);
            c0 = fmaf(-wc, v0, c0);
            c1 = fmaf(-wc, v1, c1);
        }
    }

    // final reductions fused
    float lc1 = neglog;
    float nb2 = (lane < 16) ? c0 * c0 : 0.0f;
    warp_sum2(lc1, nb2);
    float resid = fmaxf(pc2 - nb2, 0.0f);
    float LC = lc1 - 0.5f * ((float)(PK - PH) * LOG2PI + resid);

    // ---- outputs: Next_coefs [H,BP,H] | Next_biases [H,BP] | LP_new [BP] ----
    const size_t off1 = (size_t)PH * BP * PH;
    const size_t off2 = off1 + (size_t)PH * BP;

    if (lane < 16) {
        float4* po = reinterpret_cast<float4*>(out + ((size_t)lane * BP + prob) * PH);
        po[0] = make_float4(b0[0],  b0[1],  b0[2],  b0[3]);
        po[1] = make_float4(b0[4],  b0[5],  b0[6],  b0[7]);
        po[2] = make_float4(b0[8],  b0[9],  b0[10], b0[11]);
        po[3] = make_float4(b0[12], b0[13], b0[14], b0[15]);
        out[off1 + (size_t)lane * BP + prob] = c0;
    }
    if (lane == 0) {
        out[off2 + prob] = LP[prob] + LC + Log_factors[prob];
    }
}

extern "C" void kernel_launch(void* const* d_in, const int* in_sizes, int n_in,
                              void* d_out, int out_size) {
    const float* input_i     = (const float*)d_in[0];
    const float* Prev_coefs  = (const float*)d_in[1];
    const float* Prev_biases = (const float*)d_in[2];
    const float* LP          = (const float*)d_in[3];
    const float* Log_factors = (const float*)d_in[4];
    const float* obs_var     = (const float*)d_in[5];
    const float* hid_var     = (const float*)d_in[6];
    const float* next_var    = (const float*)d_in[7];
    const float* rec_biases  = (const float*)d_in[8];

    int BP = in_sizes[3];                     // B * P (size of LP)
    int blocks = (BP + WPB - 1) / WPB;        // 1 problem per warp, 4 warps/block
    integ_kernel<<<blocks, WPB * 32>>>(input_i, Prev_coefs, Prev_biases, LP, Log_factors,
                                       obs_var, hid_var, next_var, rec_biases,
                                       (float*)d_out, BP);
}

// round 16
// speedup vs baseline: 1.1757x; 1.0527x over previous
#include <cuda_runtime.h>
#include <math.h>

// Fixed shapes: B=2048, P=4, H=16, K=48, D=4, G=64
#define PH 16
#define PK 48
#define PD 4
#define LOG2PI 1.83787706640934548356f

#define SA 66              // shared row stride (floats): conflict-free
#define WPB 4              // warps (problems) per block

// unified per-warp smem layout (floats)
#define F_AT 0                       // A^T: 16 x SA
#define F_BT (16*SA)                 // [Bm|c]^T: 17 x SA          (=1056)
#define F_MM (F_BT + 17*SA)          // Gram M / Cholesky L: 16x17 (=2178)
#define F_XX (F_MM + 16*17)          // N -> X staging: 17x17      (=2450)
#define F_TOT 2756                   // X2 (dup -X, 289 u64) reuses [F_MM, F_MM+578)

typedef unsigned long long ull;

__device__ __forceinline__ ull fma2(ull a, ull b, ull c) {
    ull r;
    asm("fma.rn.f32x2 %0, %1, %2, %3;" : "=l"(r) : "l"(a), "l"(b), "l"(c));
    return r;
}
__device__ __forceinline__ ull pack2(float lo, float hi) {
    ull r;
    asm("mov.b64 %0, {%1, %2};" : "=l"(r) : "f"(lo), "f"(hi));
    return r;
}
__device__ __forceinline__ float2 unpack2(ull v) {
    float lo, hi;
    asm("mov.b64 {%0, %1}, %2;" : "=f"(lo), "=f"(hi) : "l"(v));
    return make_float2(lo, hi);
}
__device__ __forceinline__ float hadd2(ull v) { float2 f = unpack2(v); return f.x + f.y; }

__device__ __forceinline__ float warp_sum(float v) {
#pragma unroll
    for (int o = 16; o > 0; o >>= 1) v += __shfl_xor_sync(0xffffffffu, v, o);
    return v;
}
__device__ __forceinline__ void warp_sum2(float& a, float& b) {
#pragma unroll
    for (int o = 16; o > 0; o >>= 1) {
        float ta = __shfl_xor_sync(0xffffffffu, a, o);
        float tb = __shfl_xor_sync(0xffffffffu, b, o);
        a += ta; b += tb;
    }
}

// packed 64-length dot of two shared rows (8-byte aligned)
__device__ __forceinline__ float dot64(const float* p, const float* q) {
    const ull* P = reinterpret_cast<const ull*>(p);
    const ull* Q = reinterpret_cast<const ull*>(q);
    ull s0 = 0ull, s1 = 0ull;
#pragma unroll
    for (int g = 0; g < 32; g += 2) {
        s0 = fma2(P[g],   Q[g],   s0);
        s1 = fma2(P[g+1], Q[g+1], s1);
    }
    return hadd2(s0) + hadd2(s1);
}

__global__ __launch_bounds__(128, 4) void integ_kernel(
    const float* __restrict__ input_i,      // [BP, D]
    const float* __restrict__ Prev_coefs,   // [H, BP, H]
    const float* __restrict__ Prev_biases,  // [H, BP]
    const float* __restrict__ LP,           // [BP]
    const float* __restrict__ Log_factors,  // [BP]
    const float* __restrict__ obs_var,      // [K, BP, D]
    const float* __restrict__ hid_var,      // [K, BP, H]
    const float* __restrict__ next_var,     // [K, BP, H]
    const float* __restrict__ rec_biases,   // [K, BP]
    float* __restrict__ out, int BP)
{
    __shared__ float sbuf[WPB][F_TOT];

    const int warp = threadIdx.x >> 5;
    const int lane = threadIdx.x & 31;
    const int prob = blockIdx.x * WPB + warp;
    if (prob >= BP) return;

    float* At = sbuf[warp] + F_AT;
    float* Bt = sbuf[warp] + F_BT;
    float* sM = sbuf[warp] + F_MM;
    float* sX = sbuf[warp] + F_XX;
    ull*   X2 = reinterpret_cast<ull*>(sbuf[warp] + F_MM);  // reused AFTER solve

    const float4 xi = *reinterpret_cast<const float4*>(input_i + (size_t)prob * PD);

    // ---- load rows into shared (lane owns gaussians g0=lane, g1=lane+32) ----
    {
        float b0[16], b1[16], c0, c1;
        if (lane < PH) {
            const float4* p = reinterpret_cast<const float4*>(
                Prev_coefs + ((size_t)lane * BP + prob) * PH);
#pragma unroll
            for (int q = 0; q < 4; q++) {
                float4 v = p[q];
                At[(4*q+0)*SA + lane] = v.x; At[(4*q+1)*SA + lane] = v.y;
                At[(4*q+2)*SA + lane] = v.z; At[(4*q+3)*SA + lane] = v.w;
            }
#pragma unroll
            for (int i = 0; i < 16; i++) b0[i] = 0.0f;
            c0 = Prev_biases[(size_t)lane * BP + prob];
        } else {
            int k = lane - PH;
            const float4* p  = reinterpret_cast<const float4*>(
                hid_var + ((size_t)k * BP + prob) * PH);
            const float4* q4 = reinterpret_cast<const float4*>(
                next_var + ((size_t)k * BP + prob) * PH);
#pragma unroll
            for (int q = 0; q < 4; q++) {
                float4 v = p[q];
                At[(4*q+0)*SA + lane] = v.x; At[(4*q+1)*SA + lane] = v.y;
                At[(4*q+2)*SA + lane] = v.z; At[(4*q+3)*SA + lane] = v.w;
                float4 w = q4[q];
                b0[4*q+0] = w.x; b0[4*q+1] = w.y; b0[4*q+2] = w.z; b0[4*q+3] = w.w;
            }
            const float4 ov = *reinterpret_cast<const float4*>(
                obs_var + ((size_t)k * BP + prob) * PD);
            c0 = rec_biases[(size_t)k * BP + prob]
               + ov.x*xi.x + ov.y*xi.y + ov.z*xi.z + ov.w*xi.w;
        }
        {
            int k = lane + (32 - PH);
            const float4* p  = reinterpret_cast<const float4*>(
                hid_var + ((size_t)k * BP + prob) * PH);
            const float4* q4 = reinterpret_cast<const float4*>(
                next_var + ((size_t)k * BP + prob) * PH);
#pragma unroll
            for (int q = 0; q < 4; q++) {
                float4 v = p[q];
                At[(4*q+0)*SA + lane + 32] = v.x; At[(4*q+1)*SA + lane + 32] = v.y;
                At[(4*q+2)*SA + lane + 32] = v.z; At[(4*q+3)*SA + lane + 32] = v.w;
                float4 w = q4[q];
                b1[4*q+0] = w.x; b1[4*q+1] = w.y; b1[4*q+2] = w.z; b1[4*q+3] = w.w;
            }
            const float4 ov = *reinterpret_cast<const float4*>(
                obs_var + ((size_t)k * BP + prob) * PD);
            c1 = rec_biases[(size_t)k * BP + prob]
               + ov.x*xi.x + ov.y*xi.y + ov.z*xi.z + ov.w*xi.w;
        }
#pragma unroll
        for (int i = 0; i < 16; i++) {
            Bt[i*SA + lane]      = b0[i];
            Bt[i*SA + lane + 32] = b1[i];
        }
        Bt[16*SA + lane]      = c0;
        Bt[16*SA + lane + 32] = c1;
    }
    __syncwarp();

    // ---- M = A^T A : UNIFORM full 8x8 pair grid, 2 fused 2x2 tiles per lane
    //      (i-pair loaded once for both j-pairs); every entry written once. ----
    {
        int ti = lane & 7, tj = lane >> 3;    // tj in 0..3
        int i0 = 2*ti, i1 = i0 + 1;
        int jA0 = 2*tj, jA1 = jA0 + 1;
        int jB0 = 2*(tj + 4), jB1 = jB0 + 1;
        const ull* Pi0 = reinterpret_cast<const ull*>(At + i0*SA);
        const ull* Pi1 = reinterpret_cast<const ull*>(At + i1*SA);
        const ull* QA0 = reinterpret_cast<const ull*>(At + jA0*SA);
        const ull* QA1 = reinterpret_cast<const ull*>(At + jA1*SA);
        const ull* QB0 = reinterpret_cast<const ull*>(At + jB0*SA);
        const ull* QB1 = reinterpret_cast<const ull*>(At + jB1*SA);
        ull sA00=0ull, sA01=0ull, sA10=0ull, sA11=0ull;
        ull sB00=0ull, sB01=0ull, sB10=0ull, sB11=0ull;
#pragma unroll
        for (int g = 0; g < 32; g++) {
            ull u0 = Pi0[g], u1 = Pi1[g];
            ull a0 = QA0[g], a1 = QA1[g], b0v = QB0[g], b1v = QB1[g];
            sA00 = fma2(u0, a0, sA00);
            sA01 = fma2(u0, a1, sA01);
            sA10 = fma2(u1, a0, sA10);
            sA11 = fma2(u1, a1, sA11);
            sB00 = fma2(u0, b0v, sB00);
            sB01 = fma2(u0, b1v, sB01);
            sB10 = fma2(u1, b0v, sB10);
            sB11 = fma2(u1, b1v, sB11);
        }
        sM[i0*17 + jA0] = hadd2(sA00); sM[i0*17 + jA1] = hadd2(sA01);
        sM[i1*17 + jA0] = hadd2(sA10); sM[i1*17 + jA1] = hadd2(sA11);
        sM[i0*17 + jB0] = hadd2(sB00); sM[i0*17 + jB1] = hadd2(sB01);
        sM[i1*17 + jB0] = hadd2(sB10); sM[i1*17 + jB1] = hadd2(sB11);
    }
    __syncwarp();

    // ==== barrier-free region: N-Gram + bn2 overlapped with register Cholesky ====

    // ---- N = A^T Bm : FUSED 2x4 tiles (lane owns i-pair ti and k-quads tk,tk+4);
    //      A rows loaded ONCE per g for both k-quads. Bm zero rows (g<16) skipped.
    {
        int ti = lane & 7, tk = lane >> 3;
        int i0 = 2*ti, i1 = i0 + 1;
        int kA0 = 2*tk,       kA1 = kA0 + 1;
        int kB0 = 2*(tk + 4), kB1 = kB0 + 1;
        const ull* Pi0 = reinterpret_cast<const ull*>(At + i0*SA + 16);
        const ull* Pi1 = reinterpret_cast<const ull*>(At + i1*SA + 16);
        const ull* QA0 = reinterpret_cast<const ull*>(Bt + kA0*SA + 16);
        const ull* QA1 = reinterpret_cast<const ull*>(Bt + kA1*SA + 16);
        const ull* QB0 = reinterpret_cast<const ull*>(Bt + kB0*SA + 16);
        const ull* QB1 = reinterpret_cast<const ull*>(Bt + kB1*SA + 16);
        ull sA00=0ull, sA01=0ull, sA10=0ull, sA11=0ull;
        ull sB00=0ull, sB01=0ull, sB10=0ull, sB11=0ull;
#pragma unroll
        for (int g = 0; g < 24; g++) {
            ull u0 = Pi0[g], u1 = Pi1[g];
            ull a0 = QA0[g], a1 = QA1[g], b0v = QB0[g], b1v = QB1[g];
            sA00 = fma2(u0, a0, sA00);
            sA01 = fma2(u0, a1, sA01);
            sA10 = fma2(u1, a0, sA10);
            sA11 = fma2(u1, a1, sA11);
            sB00 = fma2(u0, b0v, sB00);
            sB01 = fma2(u0, b1v, sB01);
            sB10 = fma2(u1, b0v, sB10);
            sB11 = fma2(u1, b1v, sB11);
        }
        sX[kA0*17 + i0] = hadd2(sA00); sX[kA1*17 + i0] = hadd2(sA01);
        sX[kA0*17 + i1] = hadd2(sA10); sX[kA1*17 + i1] = hadd2(sA11);
        sX[kB0*17 + i0] = hadd2(sB00); sX[kB1*17 + i0] = hadd2(sB01);
        sX[kB0*17 + i1] = hadd2(sB10); sX[kB1*17 + i1] = hadd2(sB11);
    }
    // bias column k = 16 (full 64 gaussians): lanes 0..7
    if (lane < 8) {
        int i0 = 2*lane, i1 = i0 + 1;
        const ull* Pi0 = reinterpret_cast<const ull*>(At + i0*SA);
        const ull* Pi1 = reinterpret_cast<const ull*>(At + i1*SA);
        const ull* Qc  = reinterpret_cast<const ull*>(Bt + 16*SA);
        ull s0 = 0ull, s1 = 0ull;
#pragma unroll
        for (int g = 0; g < 32; g++) {
            ull u0 = Pi0[g], u1 = Pi1[g], w = Qc[g];
            s0 = fma2(u0, w, s0);
            s1 = fma2(u1, w, s1);
        }
        sX[16*17 + i0] = hadd2(s0);
        sX[16*17 + i1] = hadd2(s1);
    }

    // ---- column norms of [Bm|c] : lane k<17 owns column k ----
    float bn2 = 0.0f;
    if (lane < 17) bn2 = dot64(Bt + lane*SA, Bt + lane*SA);

    // ---- right-looking register Cholesky (rsqrt, no barriers inside) ----
    float neglog = 0.0f;
    {
        float m[16];
        int li = lane & 15;
#pragma unroll
        for (int k = 0; k < 16; k++) m[k] = sM[li*17 + k];

#pragma unroll
        for (int j = 0; j < 16; j++) {
            float d   = __shfl_sync(0xffffffffu, m[j], j);
            float rL  = rsqrtf(d);
            float lij = m[j] * rL;
            if (lane == j) {
                neglog = -0.5f * __logf(d);
                sM[j*17 + 16] = rL;
            } else if (lane > j && lane < 16) {
                sM[lane*17 + j] = lij;
            }
#pragma unroll
            for (int k = j + 1; k < 16; k++) {
                float lkj = __shfl_sync(0xffffffffu, lij, k);
                m[k] = fmaf(-lij, lkj, m[k]);
            }
        }
    }
    __syncwarp();

    // ---- solve M X = N per column (lane k<17); y stays in registers ----
    float s_own = 0.0f;
    float y[16];
    if (lane < 17) {
#pragma unroll
        for (int i = 0; i < 16; i++) y[i] = sX[lane*17 + i];
#pragma unroll
        for (int i = 0; i < 16; i++) {
            float p0 = 0.0f, p1 = 0.0f;
#pragma unroll
            for (int t = 0; t < i; t++) {
                if (t & 1) p1 = fmaf(sM[i*17 + t], y[t], p1);
                else       p0 = fmaf(sM[i*17 + t], y[t], p0);
            }
            y[i] = (y[i] - (p0 + p1)) * sM[i*17 + 16];
        }
        float qn = 0.0f;
#pragma unroll
        for (int i = 0; i < 16; i++) qn = fmaf(y[i], y[i], qn);
        s_own = bn2 - qn;
#pragma unroll
        for (int i = 15; i >= 0; i--) {
            float p0 = 0.0f, p1 = 0.0f;
#pragma unroll
            for (int t = 15; t > i; t--) {
                if (t & 1) p1 = fmaf(sM[t*17 + i], y[t], p1);
                else       p0 = fmaf(sM[t*17 + i], y[t], p0);
            }
            y[i] = (y[i] - (p0 + p1)) * sM[i*17 + 16];
        }
    }
    __syncwarp();   // all sM/sX reads done before X2 overwrites the region

    // write duplicated NEGATED X into the dead sM/sX region (one STS.64 each)
    if (lane < 17) {
#pragma unroll
        for (int i = 0; i < 16; i++) X2[lane*17 + i] = pack2(-y[i], -y[i]);
    }
    __syncwarp();

    // ---- projection: PB = Bm - A X (packed rows), Pc = c - A x_c ----
    ull bk[16], cc;
#pragma unroll
    for (int k = 0; k < 16; k++) bk[k] = pack2(Bt[k*SA + lane], Bt[k*SA + lane + 32]);
    cc = pack2(Bt[16*SA + lane], Bt[16*SA + lane + 32]);
#pragma unroll
    for (int i = 0; i < 16; i++) {
        ull ai = pack2(At[i*SA + lane], At[i*SA + lane + 32]);
#pragma unroll
        for (int k = 0; k < 16; k++) {
            bk[k] = fma2(ai, X2[k*17 + i], bk[k]);   // X2 holds -X, broadcast LDS.64
        }
        cc = fma2(ai, X2[16*17 + i], cc);
    }

    float b0[16], b1[16], c0, c1;
#pragma unroll
    for (int k = 0; k < 16; k++) {
        float2 f = unpack2(bk[k]);
        b0[k] = f.x; b1[k] = f.y;
    }
    { float2 f = unpack2(cc); c0 = f.x; c1 = f.y; }

    float pc2 = __shfl_sync(0xffffffffu, s_own, 16);   // ||Pc||^2

    // ---- Householder QR on PB (slarfg convention), norms downdated ----
#pragma unroll
    for (int j = 0; j < 16; j++) {
        float sj    = __shfl_sync(0xffffffffu, s_own, j);
        float alpha = __shfl_sync(0xffffffffu, b0[j], j);
        sj = fmaxf(sj, 1e-30f);
        float beta = -copysignf(sqrtf(sj), alpha);
        float tau  = __fdividef(beta - alpha, beta);
        float inv  = __fdividef(1.0f, alpha - beta);

        float v0 = (lane == j) ? 1.0f : ((lane > j) ? b0[j] * inv : 0.0f);
        float v1 = b1[j] * inv;

        if (lane == j)      b0[j] = beta;
        else if (lane > j)  b0[j] = 0.0f;
        b1[j] = 0.0f;

        float xc = fmaf(v0, c0, v1 * c1);

        int k = j + 1;
#pragma unroll
        for (; k + 1 < 16; k += 2) {
            float bja = __shfl_sync(0xffffffffu, b0[k],   j);
            float bjb = __shfl_sync(0xffffffffu, b0[k+1], j);
            float xa = fmaf(v0, b0[k],   v1 * b1[k]);
            float xb = fmaf(v0, b0[k+1], v1 * b1[k+1]);
            warp_sum2(xa, xb);
            float wa = tau * xa, wb = tau * xb;
            b0[k]   = fmaf(-wa, v0, b0[k]);   b1[k]   = fmaf(-wa, v1, b1[k]);
            b0[k+1] = fmaf(-wb, v0, b0[k+1]); b1[k+1] = fmaf(-wb, v1, b1[k+1]);
            float ra = bja - wa;
            float rb = bjb - wb;
            if (lane == k)   s_own = fmaf(-ra, ra, s_own);
            if (lane == k+1) s_own = fmaf(-rb, rb, s_own);
        }
        if (k < 16) {
            float bja = __shfl_sync(0xffffffffu, b0[k], j);
            float xa = fmaf(v0, b0[k], v1 * b1[k]);
            warp_sum2(xa, xc);
            float wa = tau * xa, wc = tau * xc;
            b0[k] = fmaf(-wa, v0, b0[k]);  b1[k] = fmaf(-wa, v1, b1[k]);
            c0 = fmaf(-wc, v0, c0);        c1 = fmaf(-wc, v1, c1);
            float ra = bja - wa;
            if (lane == k) s_own = fmaf(-ra, ra, s_own);
        } else {
            float wc = tau * warp_sum(xc);
            c0 = fmaf(-wc, v0, c0);
            c1 = fmaf(-wc, v1, c1);
        }
    }

    // final reductions fused
    float lc1 = neglog;
    float nb2 = (lane < 16) ? c0 * c0 : 0.0f;
    warp_sum2(lc1, nb2);
    float resid = fmaxf(pc2 - nb2, 0.0f);
    float LC = lc1 - 0.5f * ((float)(PK - PH) * LOG2PI + resid);

    // ---- outputs: Next_coefs [H,BP,H] | Next_biases [H,BP] | LP_new [BP] ----
    const size_t off1 = (size_t)PH * BP * PH;
    const size_t off2 = off1 + (size_t)PH * BP;

    if (lane < 16) {
        float4* po = reinterpret_cast<float4*>(out + ((size_t)lane * BP + prob) * PH);
        po[0] = make_float4(b0[0],  b0[1],  b0[2],  b0[3]);
        po[1] = make_float4(b0[4],  b0[5],  b0[6],  b0[7]);
        po[2] = make_float4(b0[8],  b0[9],  b0[10], b0[11]);
        po[3] = make_float4(b0[12], b0[13], b0[14], b0[15]);
        out[off1 + (size_t)lane * BP + prob] = c0;
    }
    if (lane == 0) {
        out[off2 + prob] = LP[prob] + LC + Log_factors[prob];
    }
}

extern "C" void kernel_launch(void* const* d_in, const int* in_sizes, int n_in,
                              void* d_out, int out_size) {
    const float* input_i     = (const float*)d_in[0];
    const float* Prev_coefs  = (const float*)d_in[1];
    const float* Prev_biases = (const float*)d_in[2];
    const float* LP          = (const float*)d_in[3];
    const float* Log_factors = (const float*)d_in[4];
    const float* obs_var     = (const float*)d_in[5];
    const float* hid_var     = (const float*)d_in[6];
    const float* next_var    = (const float*)d_in[7];
    const float* rec_biases  = (const float*)d_in[8];

    int BP = in_sizes[3];                     // B * P (size of LP)
    int blocks = (BP + WPB - 1) / WPB;        // 1 problem per warp, 4 warps/block
    integ_kernel<<<blocks, WPB * 32>>>(input_i, Prev_coefs, Prev_biases, LP, Log_factors,
                                       obs_var, hid_var, next_var, rec_biases,
                                       (float*)d_out, BP);
}

// round 17
// speedup vs baseline: 1.3158x; 1.1192x over previous
#include <cuda_runtime.h>
#include <math.h>

// Fixed shapes: B=2048, P=4, H=16, K=48, D=4, G=64
#define PH 16
#define PK 48
#define PD 4
#define LOG2PI 1.83787706640934548356f

#define SA 66              // shared row stride (floats): conflict-free
#define WPB 4              // warps (problems) per block

// unified per-warp smem layout (floats)
#define F_AT 0                       // A^T: 16 x SA
#define F_BT (16*SA)                 // [Bm|c]^T: 17 x SA          (=1056)
#define F_MM (F_BT + 17*SA)          // Gram M / Cholesky L: 16x17 (=2178)
#define F_XX (F_MM + 16*17)          // N -> X staging: 17x17      (=2450)
#define F_X2 2180                    // X2 i-major (-X dup), 16x18 u64, 16B-aligned
#define F_TOT 2756

typedef unsigned long long ull;

__device__ __forceinline__ ull fma2(ull a, ull b, ull c) {
    ull r;
    asm("fma.rn.f32x2 %0, %1, %2, %3;" : "=l"(r) : "l"(a), "l"(b), "l"(c));
    return r;
}
__device__ __forceinline__ ull pack2(float lo, float hi) {
    ull r;
    asm("mov.b64 %0, {%1, %2};" : "=l"(r) : "f"(lo), "f"(hi));
    return r;
}
__device__ __forceinline__ float2 unpack2(ull v) {
    float lo, hi;
    asm("mov.b64 {%0, %1}, %2;" : "=f"(lo), "=f"(hi) : "l"(v));
    return make_float2(lo, hi);
}
__device__ __forceinline__ float hadd2(ull v) { float2 f = unpack2(v); return f.x + f.y; }

__device__ __forceinline__ float warp_sum(float v) {
#pragma unroll
    for (int o = 16; o > 0; o >>= 1) v += __shfl_xor_sync(0xffffffffu, v, o);
    return v;
}
__device__ __forceinline__ void warp_sum2(float& a, float& b) {
#pragma unroll
    for (int o = 16; o > 0; o >>= 1) {
        float ta = __shfl_xor_sync(0xffffffffu, a, o);
        float tb = __shfl_xor_sync(0xffffffffu, b, o);
        a += ta; b += tb;
    }
}

// packed 64-length dot of two shared rows (8-byte aligned)
__device__ __forceinline__ float dot64(const float* p, const float* q) {
    const ull* P = reinterpret_cast<const ull*>(p);
    const ull* Q = reinterpret_cast<const ull*>(q);
    ull s0 = 0ull, s1 = 0ull;
#pragma unroll
    for (int g = 0; g < 32; g += 2) {
        s0 = fma2(P[g],   Q[g],   s0);
        s1 = fma2(P[g+1], Q[g+1], s1);
    }
    return hadd2(s0) + hadd2(s1);
}

__global__ __launch_bounds__(128, 4) void integ_kernel(
    const float* __restrict__ input_i,      // [BP, D]
    const float* __restrict__ Prev_coefs,   // [H, BP, H]
    const float* __restrict__ Prev_biases,  // [H, BP]
    const float* __restrict__ LP,           // [BP]
    const float* __restrict__ Log_factors,  // [BP]
    const float* __restrict__ obs_var,      // [K, BP, D]
    const float* __restrict__ hid_var,      // [K, BP, H]
    const float* __restrict__ next_var,     // [K, BP, H]
    const float* __restrict__ rec_biases,   // [K, BP]
    float* __restrict__ out, int BP)
{
    __shared__ float sbuf[WPB][F_TOT];

    const int warp = threadIdx.x >> 5;
    const int lane = threadIdx.x & 31;
    const int prob = blockIdx.x * WPB + warp;
    if (prob >= BP) return;

    float* At  = sbuf[warp] + F_AT;
    float* Bt  = sbuf[warp] + F_BT;
    float* sM  = sbuf[warp] + F_MM;
    float* sX  = sbuf[warp] + F_XX;
    ull*   X2b = reinterpret_cast<ull*>(sbuf[warp] + F_X2);  // i-major, AFTER solve

    const float4 xi = *reinterpret_cast<const float4*>(input_i + (size_t)prob * PD);

    // ---- load rows into shared (lane owns gaussians g0=lane, g1=lane+32) ----
    {
        float b0[16], b1[16], c0, c1;
        if (lane < PH) {
            const float4* p = reinterpret_cast<const float4*>(
                Prev_coefs + ((size_t)lane * BP + prob) * PH);
#pragma unroll
            for (int q = 0; q < 4; q++) {
                float4 v = p[q];
                At[(4*q+0)*SA + lane] = v.x; At[(4*q+1)*SA + lane] = v.y;
                At[(4*q+2)*SA + lane] = v.z; At[(4*q+3)*SA + lane] = v.w;
            }
#pragma unroll
            for (int i = 0; i < 16; i++) b0[i] = 0.0f;
            c0 = Prev_biases[(size_t)lane * BP + prob];
        } else {
            int k = lane - PH;
            const float4* p  = reinterpret_cast<const float4*>(
                hid_var + ((size_t)k * BP + prob) * PH);
            const float4* q4 = reinterpret_cast<const float4*>(
                next_var + ((size_t)k * BP + prob) * PH);
#pragma unroll
            for (int q = 0; q < 4; q++) {
                float4 v = p[q];
                At[(4*q+0)*SA + lane] = v.x; At[(4*q+1)*SA + lane] = v.y;
                At[(4*q+2)*SA + lane] = v.z; At[(4*q+3)*SA + lane] = v.w;
                float4 w = q4[q];
                b0[4*q+0] = w.x; b0[4*q+1] = w.y; b0[4*q+2] = w.z; b0[4*q+3] = w.w;
            }
            const float4 ov = *reinterpret_cast<const float4*>(
                obs_var + ((size_t)k * BP + prob) * PD);
            c0 = rec_biases[(size_t)k * BP + prob]
               + ov.x*xi.x + ov.y*xi.y + ov.z*xi.z + ov.w*xi.w;
        }
        {
            int k = lane + (32 - PH);
            const float4* p  = reinterpret_cast<const float4*>(
                hid_var + ((size_t)k * BP + prob) * PH);
            const float4* q4 = reinterpret_cast<const float4*>(
                next_var + ((size_t)k * BP + prob) * PH);
#pragma unroll
            for (int q = 0; q < 4; q++) {
                float4 v = p[q];
                At[(4*q+0)*SA + lane + 32] = v.x; At[(4*q+1)*SA + lane + 32] = v.y;
                At[(4*q+2)*SA + lane + 32] = v.z; At[(4*q+3)*SA + lane + 32] = v.w;
                float4 w = q4[q];
                b1[4*q+0] = w.x; b1[4*q+1] = w.y; b1[4*q+2] = w.z; b1[4*q+3] = w.w;
            }
            const float4 ov = *reinterpret_cast<const float4*>(
                obs_var + ((size_t)k * BP + prob) * PD);
            c1 = rec_biases[(size_t)k * BP + prob]
               + ov.x*xi.x + ov.y*xi.y + ov.z*xi.z + ov.w*xi.w;
        }
#pragma unroll
        for (int i = 0; i < 16; i++) {
            Bt[i*SA + lane]      = b0[i];
            Bt[i*SA + lane + 32] = b1[i];
        }
        Bt[16*SA + lane]      = c0;
        Bt[16*SA + lane + 32] = c1;
    }
    __syncwarp();

    // ---- M = A^T A : UNIFORM full 8x8 pair grid, 2 fused 2x2 tiles per lane ----
    {
        int ti = lane & 7, tj = lane >> 3;    // tj in 0..3
        int i0 = 2*ti, i1 = i0 + 1;
        int jA0 = 2*tj, jA1 = jA0 + 1;
        int jB0 = 2*(tj + 4), jB1 = jB0 + 1;
        const ull* Pi0 = reinterpret_cast<const ull*>(At + i0*SA);
        const ull* Pi1 = reinterpret_cast<const ull*>(At + i1*SA);
        const ull* QA0 = reinterpret_cast<const ull*>(At + jA0*SA);
        const ull* QA1 = reinterpret_cast<const ull*>(At + jA1*SA);
        const ull* QB0 = reinterpret_cast<const ull*>(At + jB0*SA);
        const ull* QB1 = reinterpret_cast<const ull*>(At + jB1*SA);
        ull sA00=0ull, sA01=0ull, sA10=0ull, sA11=0ull;
        ull sB00=0ull, sB01=0ull, sB10=0ull, sB11=0ull;
#pragma unroll
        for (int g = 0; g < 32; g++) {
            ull u0 = Pi0[g], u1 = Pi1[g];
            ull a0 = QA0[g], a1 = QA1[g], b0v = QB0[g], b1v = QB1[g];
            sA00 = fma2(u0, a0, sA00);
            sA01 = fma2(u0, a1, sA01);
            sA10 = fma2(u1, a0, sA10);
            sA11 = fma2(u1, a1, sA11);
            sB00 = fma2(u0, b0v, sB00);
            sB01 = fma2(u0, b1v, sB01);
            sB10 = fma2(u1, b0v, sB10);
            sB11 = fma2(u1, b1v, sB11);
        }
        sM[i0*17 + jA0] = hadd2(sA00); sM[i0*17 + jA1] = hadd2(sA01);
        sM[i1*17 + jA0] = hadd2(sA10); sM[i1*17 + jA1] = hadd2(sA11);
        sM[i0*17 + jB0] = hadd2(sB00); sM[i0*17 + jB1] = hadd2(sB01);
        sM[i1*17 + jB0] = hadd2(sB10); sM[i1*17 + jB1] = hadd2(sB11);
    }
    __syncwarp();

    // ==== barrier-free region: N-Gram + bn2 overlapped with register Cholesky ====

    // ---- N = A^T Bm : FUSED 2x4 tiles; Bm zero rows (g<16) skipped ----
    {
        int ti = lane & 7, tk = lane >> 3;
        int i0 = 2*ti, i1 = i0 + 1;
        int kA0 = 2*tk,       kA1 = kA0 + 1;
        int kB0 = 2*(tk + 4), kB1 = kB0 + 1;
        const ull* Pi0 = reinterpret_cast<const ull*>(At + i0*SA + 16);
        const ull* Pi1 = reinterpret_cast<const ull*>(At + i1*SA + 16);
        const ull* QA0 = reinterpret_cast<const ull*>(Bt + kA0*SA + 16);
        const ull* QA1 = reinterpret_cast<const ull*>(Bt + kA1*SA + 16);
        const ull* QB0 = reinterpret_cast<const ull*>(Bt + kB0*SA + 16);
        const ull* QB1 = reinterpret_cast<const ull*>(Bt + kB1*SA + 16);
        ull sA00=0ull, sA01=0ull, sA10=0ull, sA11=0ull;
        ull sB00=0ull, sB01=0ull, sB10=0ull, sB11=0ull;
#pragma unroll
        for (int g = 0; g < 24; g++) {
            ull u0 = Pi0[g], u1 = Pi1[g];
            ull a0 = QA0[g], a1 = QA1[g], b0v = QB0[g], b1v = QB1[g];
            sA00 = fma2(u0, a0, sA00);
            sA01 = fma2(u0, a1, sA01);
            sA10 = fma2(u1, a0, sA10);
            sA11 = fma2(u1, a1, sA11);
            sB00 = fma2(u0, b0v, sB00);
            sB01 = fma2(u0, b1v, sB01);
            sB10 = fma2(u1, b0v, sB10);
            sB11 = fma2(u1, b1v, sB11);
        }
        sX[kA0*17 + i0] = hadd2(sA00); sX[kA1*17 + i0] = hadd2(sA01);
        sX[kA0*17 + i1] = hadd2(sA10); sX[kA1*17 + i1] = hadd2(sA11);
        sX[kB0*17 + i0] = hadd2(sB00); sX[kB1*17 + i0] = hadd2(sB01);
        sX[kB0*17 + i1] = hadd2(sB10); sX[kB1*17 + i1] = hadd2(sB11);
    }
    // bias column k = 16 (full 64 gaussians): lanes 0..7
    if (lane < 8) {
        int i0 = 2*lane, i1 = i0 + 1;
        const ull* Pi0 = reinterpret_cast<const ull*>(At + i0*SA);
        const ull* Pi1 = reinterpret_cast<const ull*>(At + i1*SA);
        const ull* Qc  = reinterpret_cast<const ull*>(Bt + 16*SA);
        ull s0 = 0ull, s1 = 0ull;
#pragma unroll
        for (int g = 0; g < 32; g++) {
            ull u0 = Pi0[g], u1 = Pi1[g], w = Qc[g];
            s0 = fma2(u0, w, s0);
            s1 = fma2(u1, w, s1);
        }
        sX[16*17 + i0] = hadd2(s0);
        sX[16*17 + i1] = hadd2(s1);
    }

    // ---- column norms of [Bm|c] : lane k<17 owns column k ----
    float bn2 = 0.0f;
    if (lane < 17) bn2 = dot64(Bt + lane*SA, Bt + lane*SA);

    // ---- right-looking register Cholesky (rsqrt, no barriers inside) ----
    float neglog = 0.0f;
    {
        float m[16];
        int li = lane & 15;
#pragma unroll
        for (int k = 0; k < 16; k++) m[k] = sM[li*17 + k];

#pragma unroll
        for (int j = 0; j < 16; j++) {
            float d   = __shfl_sync(0xffffffffu, m[j], j);
            float rL  = rsqrtf(d);
            float lij = m[j] * rL;
            if (lane == j) {
                neglog = -0.5f * __logf(d);
                sM[j*17 + 16] = rL;
            } else if (lane > j && lane < 16) {
                sM[lane*17 + j] = lij;
            }
#pragma unroll
            for (int k = j + 1; k < 16; k++) {
                float lkj = __shfl_sync(0xffffffffu, lij, k);
                m[k] = fmaf(-lij, lkj, m[k]);
            }
        }
    }
    __syncwarp();

    // ---- solve M X = N per column (lane k<17); y stays in registers ----
    float s_own = 0.0f;
    float y[16];
    if (lane < 17) {
#pragma unroll
        for (int i = 0; i < 16; i++) y[i] = sX[lane*17 + i];
#pragma unroll
        for (int i = 0; i < 16; i++) {
            float p0 = 0.0f, p1 = 0.0f;
#pragma unroll
            for (int t = 0; t < i; t++) {
                if (t & 1) p1 = fmaf(sM[i*17 + t], y[t], p1);
                else       p0 = fmaf(sM[i*17 + t], y[t], p0);
            }
            y[i] = (y[i] - (p0 + p1)) * sM[i*17 + 16];
        }
        float qn = 0.0f;
#pragma unroll
        for (int i = 0; i < 16; i++) qn = fmaf(y[i], y[i], qn);
        s_own = bn2 - qn;
#pragma unroll
        for (int i = 15; i >= 0; i--) {
            float p0 = 0.0f, p1 = 0.0f;
#pragma unroll
            for (int t = 15; t > i; t--) {
                if (t & 1) p1 = fmaf(sM[t*17 + i], y[t], p1);
                else       p0 = fmaf(sM[t*17 + i], y[t], p0);
            }
            y[i] = (y[i] - (p0 + p1)) * sM[i*17 + 16];
        }
    }
    __syncwarp();   // all sM/sX reads done before X2b overwrites the region

    // write duplicated NEGATED X, i-major (stride 18 u64): one STS.64 per i
    if (lane < 17) {
#pragma unroll
        for (int i = 0; i < 16; i++) X2b[i*18 + lane] = pack2(-y[i], -y[i]);
    }
    __syncwarp();

    // ---- projection: PB = Bm - A X (packed rows), Pc = c - A x_c ----
    //      X row i is contiguous -> 8 LDS.128 + 1 LDS.64 per i (vs 17 LDS.64).
    ull bk[16], cc;
#pragma unroll
    for (int k = 0; k < 16; k++) bk[k] = pack2(Bt[k*SA + lane], Bt[k*SA + lane + 32]);
    cc = pack2(Bt[16*SA + lane], Bt[16*SA + lane + 32]);
#pragma unroll
    for (int i = 0; i < 16; i++) {
        ull ai = pack2(At[i*SA + lane], At[i*SA + lane + 32]);
        const ulonglong2* Xp = reinterpret_cast<const ulonglong2*>(X2b + i*18);
#pragma unroll
        for (int kk = 0; kk < 8; kk++) {
            ulonglong2 xv = Xp[kk];
            bk[2*kk]   = fma2(ai, xv.x, bk[2*kk]);
            bk[2*kk+1] = fma2(ai, xv.y, bk[2*kk+1]);
        }
        cc = fma2(ai, X2b[i*18 + 16], cc);
    }

    float b0[16], b1[16], c0, c1;
#pragma unroll
    for (int k = 0; k < 16; k++) {
        float2 f = unpack2(bk[k]);
        b0[k] = f.x; b1[k] = f.y;
    }
    { float2 f = unpack2(cc); c0 = f.x; c1 = f.y; }

    float pc2 = __shfl_sync(0xffffffffu, s_own, 16);   // ||Pc||^2

    // ---- Householder QR on PB (slarfg convention), norms downdated ----
#pragma unroll
    for (int j = 0; j < 16; j++) {
        float sj    = __shfl_sync(0xffffffffu, s_own, j);
        float alpha = __shfl_sync(0xffffffffu, b0[j], j);
        sj = fmaxf(sj, 1e-30f);
        float beta = -copysignf(sqrtf(sj), alpha);
        float tau  = __fdividef(beta - alpha, beta);
        float inv  = __fdividef(1.0f, alpha - beta);

        float v0 = (lane == j) ? 1.0f : ((lane > j) ? b0[j] * inv : 0.0f);
        float v1 = b1[j] * inv;

        if (lane == j)      b0[j] = beta;
        else if (lane > j)  b0[j] = 0.0f;
        b1[j] = 0.0f;

        float xc = fmaf(v0, c0, v1 * c1);

        int k = j + 1;
#pragma unroll
        for (; k + 1 < 16; k += 2) {
            float bja = __shfl_sync(0xffffffffu, b0[k],   j);
            float bjb = __shfl_sync(0xffffffffu, b0[k+1], j);
            float xa = fmaf(v0, b0[k],   v1 * b1[k]);
            float xb = fmaf(v0, b0[k+1], v1 * b1[k+1]);
            warp_sum2(xa, xb);
            float wa = tau * xa, wb = tau * xb;
            b0[k]   = fmaf(-wa, v0, b0[k]);   b1[k]   = fmaf(-wa, v1, b1[k]);
            b0[k+1] = fmaf(-wb, v0, b0[k+1]); b1[k+1] = fmaf(-wb, v1, b1[k+1]);
            float ra = bja - wa;
            float rb = bjb - wb;
            if (lane == k)   s_own = fmaf(-ra, ra, s_own);
            if (lane == k+1) s_own = fmaf(-rb, rb, s_own);
        }
        if (k < 16) {
            float bja = __shfl_sync(0xffffffffu, b0[k], j);
            float xa = fmaf(v0, b0[k], v1 * b1[k]);
            warp_sum2(xa, xc);
            float wa = tau * xa, wc = tau * xc;
            b0[k] = fmaf(-wa, v0, b0[k]);  b1[k] = fmaf(-wa, v1, b1[k]);
            c0 = fmaf(-wc, v0, c0);        c1 = fmaf(-wc, v1, c1);
            float ra = bja - wa;
            if (lane == k) s_own = fmaf(-ra, ra, s_own);
        } else {
            float wc = tau * warp_sum(xc);
            c0 = fmaf(-wc, v0, c0);
            c1 = fmaf(-wc, v1, c1);
        }
    }

    // final reductions fused
    float lc1 = neglog;
    float nb2 = (lane < 16) ? c0 * c0 : 0.0f;
    warp_sum2(lc1, nb2);
    float resid = fmaxf(pc2 - nb2, 0.0f);
    float LC = lc1 - 0.5f * ((float)(PK - PH) * LOG2PI + resid);

    // ---- outputs: Next_coefs [H,BP,H] | Next_biases [H,BP] | LP_new [BP] ----
    const size_t off1 = (size_t)PH * BP * PH;
    const size_t off2 = off1 + (size_t)PH * BP;

    if (lane < 16) {
        float4* po = reinterpret_cast<float4*>(out + ((size_t)lane * BP + prob) * PH);
        po[0] = make_float4(b0[0],  b0[1],  b0[2],  b0[3]);
        po[1] = make_float4(b0[4],  b0[5],  b0[6],  b0[7]);
        po[2] = make_float4(b0[8],  b0[9],  b0[10], b0[11]);
        po[3] = make_float4(b0[12], b0[13], b0[14], b0[15]);
        out[off1 + (size_t)lane * BP + prob] = c0;
    }
    if (lane == 0) {
        out[off2 + prob] = LP[prob] + LC + Log_factors[prob];
    }
}

extern "C" void kernel_launch(void* const* d_in, const int* in_sizes, int n_in,
                              void* d_out, int out_size) {
    const float* input_i     = (const float*)d_in[0];
    const float* Prev_coefs  = (const float*)d_in[1];
    const float* Prev_biases = (const float*)d_in[2];
    const float* LP          = (const float*)d_in[3];
    const float* Log_factors = (const float*)d_in[4];
    const float* obs_var     = (const float*)d_in[5];
    const float* hid_var     = (const float*)d_in[6];
    const float* next_var    = (const float*)d_in[7];
    const float* rec_biases  = (const float*)d_in[8];

    int BP = in_sizes[3];                     // B * P (size of LP)
    int blocks = (BP + WPB - 1) / WPB;        // 1 problem per warp, 4 warps/block
    integ_kernel<<<blocks, WPB * 32>>>(input_i, Prev_coefs, Prev_biases, LP, Log_factors,
                                       obs_var, hid_var, next_var, rec_biases,
                                       (float*)d_out, BP);
}